// round 13
// baseline (speedup 1.0000x reference)
#include <cuda_runtime.h>
#include <math.h>
#include <stdint.h>

#define NN   100000
#define EE   3200000
#define FIN  128
#define DIMR 95
#define DIMP 96
#define GG   256
#define FC2  190
#define NEG  0.2f
#define BNEPS 1e-5f
#define NBLK 98              // ceil(NN/1024)

// ---------------- scratch (device globals; no allocation allowed) ----------------
__device__ float g_y  [(size_t)NN * DIMP];     // x @ w1a (pre-aggregation)
__device__ float g_t1 [(size_t)NN * DIMP];     // relu(y_i + sum y_j + b1a)
__device__ float g_h  [(size_t)NN * DIMP];     // BN(relu(t1@w1b+b1b))
__device__ float g_ht [(size_t)NN * DIMP];     // h@wg
__device__ float g_ao [(size_t)NN * DIMP];     // GAT out
__device__ float g_als[NN], g_ald[NN];
__device__ float g_gp [GG * DIMP];
__device__ int   g_deg[NN];
__device__ int   g_bsum[128];
__device__ int   g_boff[128];
__device__ int   g_rowptr[NN + 1];
__device__ int   g_cursor[NN];
__device__ int   g_col[EE];
__device__ float g_W1[FIN * DIMP];
__device__ float g_W2[DIMP * DIMP];
__device__ float g_W3[DIMP * DIMP];
__device__ float g_B1[DIMP], g_B2[DIMP], g_BNS[DIMP], g_BNT[DIMP];
__device__ float g_ASRC[DIMP], g_ADST[DIMP], g_BG[DIMP];
__device__ int   g_is64;    // 1 if edge_index/batch are int64, 0 if int32

__device__ __forceinline__ float lrelu(float v) { return v > 0.f ? v : NEG * v; }

__device__ __forceinline__ unsigned f2tf32(float f)
{
    unsigned u;
    asm("cvt.rna.tf32.f32 %0, %1;" : "=r"(u) : "f"(f));
    return u;
}

// ---------------- dtype detection ----------------
__global__ void detect_kernel(const int* __restrict__ ei32)
{
    int tid = threadIdx.x;   // 256 threads
    int ok = (ei32[2 * tid + 1] == 0) ? 1 : 0;
    int cnt = __syncthreads_count(ok);
    if (tid == 0) g_is64 = (cnt == 256) ? 1 : 0;
}

template<typename T>
__device__ __forceinline__ bool type_active() { return g_is64 == (sizeof(T) == 8 ? 1 : 0); }

// ---------------- weight prep: pad everything to width 96, fold BN ----------------
__global__ void prep_kernel(const float* __restrict__ w1a, const float* __restrict__ b1a,
                            const float* __restrict__ w1b, const float* __restrict__ b1b,
                            const float* __restrict__ bng, const float* __restrict__ bnb,
                            const float* __restrict__ bnm, const float* __restrict__ bnv,
                            const float* __restrict__ wg,  const float* __restrict__ bg,
                            const float* __restrict__ asrc,const float* __restrict__ adst)
{
    int i = blockIdx.x * blockDim.x + threadIdx.x;
    if (i < FIN * DIMP) {
        int r = i / DIMP, c = i % DIMP;
        g_W1[i] = (c < DIMR) ? w1a[r * DIMR + c] : 0.f;
    }
    if (i < DIMP * DIMP) {
        int r = i / DIMP, c = i % DIMP;
        bool ok = (r < DIMR && c < DIMR);
        g_W2[i] = ok ? w1b[r * DIMR + c] : 0.f;
        g_W3[i] = ok ? wg [r * DIMR + c] : 0.f;
    }
    if (i < DIMP) {
        bool ok = i < DIMR;
        g_B1[i] = ok ? b1a[i] : 0.f;
        g_B2[i] = ok ? b1b[i] : 0.f;
        float s = ok ? bng[i] * rsqrtf(bnv[i] + BNEPS) : 0.f;
        g_BNS[i] = s;
        g_BNT[i] = ok ? (bnb[i] - bnm[i] * s) : 0.f;
        g_ASRC[i] = ok ? asrc[i] : 0.f;
        g_ADST[i] = ok ? adst[i] : 0.f;
        g_BG[i]   = ok ? bg[i]   : 0.f;
    }
}

// ---------------- CSR build ----------------
__global__ void zero_deg_kernel()
{
    int i = blockIdx.x * blockDim.x + threadIdx.x;
    if (i < NN) g_deg[i] = 0;
}

template<typename T>
__global__ void hist_kernel(const void* __restrict__ eiv)
{
    if (!type_active<T>()) return;
    const T* __restrict__ ei = (const T*)eiv;
    int e = blockIdx.x * blockDim.x + threadIdx.x;
    if (e < EE) atomicAdd(&g_deg[(int)ei[EE + e]], 1);
}

__device__ __forceinline__ int warp_incl_scan(int v, int lane)
{
#pragma unroll
    for (int o = 1; o < 32; o <<= 1) {
        int t = __shfl_up_sync(0xffffffffu, v, o);
        if (lane >= o) v += t;
    }
    return v;
}

__global__ void block_sum_kernel()
{
    int blk = blockIdx.x, tid = threadIdx.x;           // 256 threads
    int lane = tid & 31, wid = tid >> 5;
    int i0 = blk * 1024 + tid * 4;
    int s = 0;
#pragma unroll
    for (int k = 0; k < 4; k++) {
        int i = i0 + k;
        if (i < NN) s += g_deg[i];
    }
#pragma unroll
    for (int o = 16; o; o >>= 1) s += __shfl_xor_sync(0xffffffffu, s, o);
    __shared__ int ws[8];
    if (lane == 0) ws[wid] = s;
    __syncthreads();
    if (tid == 0) {
        int t = 0;
        for (int w = 0; w < 8; w++) t += ws[w];
        g_bsum[blk] = t;
    }
}

__global__ void scan_partials_kernel()
{
    __shared__ int sm[128];
    int tid = threadIdx.x;
    int v = (tid < NBLK) ? g_bsum[tid] : 0;
    sm[tid] = v;
    __syncthreads();
#pragma unroll
    for (int o = 1; o < 128; o <<= 1) {
        int t = (tid >= o) ? sm[tid - o] : 0;
        __syncthreads();
        sm[tid] += t;
        __syncthreads();
    }
    if (tid < NBLK) g_boff[tid] = sm[tid] - v;
}

__global__ void rowptr_kernel()
{
    int blk = blockIdx.x, tid = threadIdx.x;           // 256 threads
    int lane = tid & 31, wid = tid >> 5;
    int i0 = blk * 1024 + tid * 4;
    int v[4];
#pragma unroll
    for (int k = 0; k < 4; k++) {
        int i = i0 + k;
        v[k] = (i < NN) ? g_deg[i] : 0;
    }
    int tsum = v[0] + v[1] + v[2] + v[3];
    int incl = warp_incl_scan(tsum, lane);
    __shared__ int ws[8];
    if (lane == 31) ws[wid] = incl;
    __syncthreads();
    if (wid == 0) {
        int w = (lane < 8) ? ws[lane] : 0;
        int wi = warp_incl_scan(w, lane);
        if (lane < 8) ws[lane] = wi - w;   // exclusive warp offsets
    }
    __syncthreads();
    int base = g_boff[blk] + ws[wid] + (incl - tsum);
    int pre = 0;
#pragma unroll
    for (int k = 0; k < 4; k++) {
        int i = i0 + k;
        if (i < NN) {
            int excl = base + pre;
            g_rowptr[i] = excl;
            g_cursor[i] = excl;
            if (i == NN - 1) g_rowptr[NN] = excl + v[k];
        }
        pre += v[k];
    }
}

template<typename T>
__global__ void scatter_kernel(const void* __restrict__ eiv)
{
    if (!type_active<T>()) return;
    const T* __restrict__ ei = (const T*)eiv;
    int e = blockIdx.x * blockDim.x + threadIdx.x;
    if (e < EE) {
        int d = (int)ei[EE + e];
        int p = atomicAdd(&g_cursor[d], 1);
        g_col[p] = (int)ei[e];
    }
}

// ---------------- GIN aggregation (96-wide, post-GEMM): warp per node, float4 ------
__global__ void gin_agg_kernel()
{
    int n = (blockIdx.x * blockDim.x + threadIdx.x) >> 5;
    int lane = threadIdx.x & 31;
    if (n >= NN) return;
    int p0 = g_rowptr[n], p1 = g_rowptr[n + 1];
    const float4* __restrict__ y4 = (const float4*)g_y;
    if (lane < 24) {
        float4 acc = y4[(size_t)n * 24 + lane];
        for (int p = p0; p < p1; p++) {
            int s = g_col[p];
            float4 v = y4[(size_t)s * 24 + lane];
            acc.x += v.x; acc.y += v.y; acc.z += v.z; acc.w += v.w;
        }
        float4 bb = ((const float4*)g_B1)[lane];
        float4 o;
        o.x = fmaxf(acc.x + bb.x, 0.f);
        o.y = fmaxf(acc.y + bb.y, 0.f);
        o.z = fmaxf(acc.z + bb.z, 0.f);
        o.w = fmaxf(acc.w + bb.w, 0.f);
        ((float4*)g_t1)[(size_t)n * 24 + lane] = o;
    }
}

// ---------------- 3xTF32 tensor-core GEMM: C[M,96] = epi(A[M,K] @ W[K,96]) ---------
// BM=64, BN=96, BK=16, 256 threads = 8 warps (4 M-slabs x 2 N-slabs of 48).
// Hi/lo tf32 split done in the tile loader; inner loop = LDS + mma.sync only.
// D += Ahi*Bhi + Alo*Bhi + Ahi*Blo   (3xTF32, fp32-class accuracy)
// MODE 0: A=x(ext) K=128 W=g_W1 C=g_y  epi=plain
// MODE 1: A=g_t1   K=96  W=g_W2 C=g_h  epi=BN(relu+bias)
// MODE 2: A=g_h    K=96  W=g_W3 C=g_ht epi=plain
template<int MODE>
__global__ __launch_bounds__(256, 3)
void gemm_kernel(const float* __restrict__ Aext)
{
    const float* __restrict__ A = (MODE == 0) ? Aext : (MODE == 1) ? g_t1 : g_h;
    const float* __restrict__ W = (MODE == 0) ? g_W1 : (MODE == 1) ? g_W2 : g_W3;
    float* __restrict__ C       = (MODE == 0) ? g_y  : (MODE == 1) ? g_h  : g_ht;
    const int K = (MODE == 0) ? FIN : DIMP;
    const int M = NN;

    __shared__ float Ah[2][16][68], Al[2][16][68];      // [k][row], pad 68
    __shared__ __align__(16) float Bh[2][16][100], Bl[2][16][100]; // [k][col], pad 100

    int tid = threadIdx.x;
    int w = tid >> 5, lane = tid & 31;
    int g = lane >> 2, t = lane & 3;
    int mbase = (w & 3) * 16;          // warp M-slab
    int nbase = (w >> 2) * 48;         // warp N-slab
    int r0 = blockIdx.x * 64;

    // A-load geometry: 64x16 tile = 256 float4, 1 per thread
    const int arow = tid >> 2, akq = tid & 3;
    const int gra = r0 + arow;
    // B-load geometry: 384 float4; tid and tid+256 (if <384)
    const int brow0 = tid / 24,  bc0 = tid % 24;
    const bool bv1 = (tid + 256) < 384;
    const int brow1 = (tid + 256) / 24, bc1 = (tid + 256) % 24;

    float4 pa, pb0, pb1;
    const float4 z4 = make_float4(0.f, 0.f, 0.f, 0.f);

    pa  = (gra < M) ? *(const float4*)(A + (size_t)gra * K + akq * 4) : z4;
    pb0 = *(const float4*)(W + (size_t)brow0 * 96 + bc0 * 4);
    pb1 = bv1 ? *(const float4*)(W + (size_t)brow1 * 96 + bc1 * 4) : z4;

    // split+store helpers (macro-free, inlined)
    auto storeA = [&](int buf, const float4& v) {
        float vv[4] = {v.x, v.y, v.z, v.w};
#pragma unroll
        for (int q = 0; q < 4; q++) {
            float hi = __uint_as_float(f2tf32(vv[q]));
            Ah[buf][akq * 4 + q][arow] = hi;
            Al[buf][akq * 4 + q][arow] = __uint_as_float(f2tf32(vv[q] - hi));
        }
    };
    auto storeB = [&](int buf, int row, int c, const float4& v) {
        float hx = __uint_as_float(f2tf32(v.x));
        float hy = __uint_as_float(f2tf32(v.y));
        float hz = __uint_as_float(f2tf32(v.z));
        float hw = __uint_as_float(f2tf32(v.w));
        *(float4*)(&Bh[buf][row][c * 4]) = make_float4(hx, hy, hz, hw);
        *(float4*)(&Bl[buf][row][c * 4]) = make_float4(
            __uint_as_float(f2tf32(v.x - hx)), __uint_as_float(f2tf32(v.y - hy)),
            __uint_as_float(f2tf32(v.z - hz)), __uint_as_float(f2tf32(v.w - hw)));
    };

    storeA(0, pa);
    storeB(0, brow0, bc0, pb0);
    if (bv1) storeB(0, brow1, bc1, pb1);
    __syncthreads();

    float acc[6][4];
#pragma unroll
    for (int j = 0; j < 6; j++)
#pragma unroll
        for (int q = 0; q < 4; q++) acc[j][q] = 0.f;

    const int ntile = K >> 4;
#pragma unroll 1
    for (int kt = 0; kt < ntile; kt++) {
        int cur = kt & 1, nxt = cur ^ 1;
        bool more = (kt + 1) < ntile;
        if (more) {
            int kb = (kt + 1) * 16;
            pa  = (gra < M) ? *(const float4*)(A + (size_t)gra * K + kb + akq * 4) : z4;
            pb0 = *(const float4*)(W + (size_t)(kb + brow0) * 96 + bc0 * 4);
            pb1 = bv1 ? *(const float4*)(W + (size_t)(kb + brow1) * 96 + bc1 * 4) : z4;
        }
#pragma unroll
        for (int k8 = 0; k8 < 2; k8++) {
            int k0 = k8 * 8;
            // A fragments (m16k8): a0=(g,t) a1=(g+8,t) a2=(g,t+4) a3=(g+8,t+4)
            unsigned ah0 = __float_as_uint(Ah[cur][k0 + t][mbase + g]);
            unsigned ah1 = __float_as_uint(Ah[cur][k0 + t][mbase + g + 8]);
            unsigned ah2 = __float_as_uint(Ah[cur][k0 + t + 4][mbase + g]);
            unsigned ah3 = __float_as_uint(Ah[cur][k0 + t + 4][mbase + g + 8]);
            unsigned al0 = __float_as_uint(Al[cur][k0 + t][mbase + g]);
            unsigned al1 = __float_as_uint(Al[cur][k0 + t][mbase + g + 8]);
            unsigned al2 = __float_as_uint(Al[cur][k0 + t + 4][mbase + g]);
            unsigned al3 = __float_as_uint(Al[cur][k0 + t + 4][mbase + g + 8]);
#pragma unroll
            for (int j = 0; j < 6; j++) {
                int c = nbase + j * 8 + g;
                unsigned bh0 = __float_as_uint(Bh[cur][k0 + t][c]);
                unsigned bh1 = __float_as_uint(Bh[cur][k0 + t + 4][c]);
                unsigned bl0 = __float_as_uint(Bl[cur][k0 + t][c]);
                unsigned bl1 = __float_as_uint(Bl[cur][k0 + t + 4][c]);
                asm("mma.sync.aligned.m16n8k8.row.col.f32.tf32.tf32.f32 "
                    "{%0,%1,%2,%3}, {%4,%5,%6,%7}, {%8,%9}, {%0,%1,%2,%3};"
                    : "+f"(acc[j][0]), "+f"(acc[j][1]), "+f"(acc[j][2]), "+f"(acc[j][3])
                    : "r"(ah0), "r"(ah1), "r"(ah2), "r"(ah3), "r"(bh0), "r"(bh1));
                asm("mma.sync.aligned.m16n8k8.row.col.f32.tf32.tf32.f32 "
                    "{%0,%1,%2,%3}, {%4,%5,%6,%7}, {%8,%9}, {%0,%1,%2,%3};"
                    : "+f"(acc[j][0]), "+f"(acc[j][1]), "+f"(acc[j][2]), "+f"(acc[j][3])
                    : "r"(al0), "r"(al1), "r"(al2), "r"(al3), "r"(bh0), "r"(bh1));
                asm("mma.sync.aligned.m16n8k8.row.col.f32.tf32.tf32.f32 "
                    "{%0,%1,%2,%3}, {%4,%5,%6,%7}, {%8,%9}, {%0,%1,%2,%3};"
                    : "+f"(acc[j][0]), "+f"(acc[j][1]), "+f"(acc[j][2]), "+f"(acc[j][3])
                    : "r"(ah0), "r"(ah1), "r"(ah2), "r"(ah3), "r"(bl0), "r"(bl1));
            }
        }
        if (more) {
            storeA(nxt, pa);
            storeB(nxt, brow0, bc0, pb0);
            if (bv1) storeB(nxt, brow1, bc1, pb1);
            __syncthreads();
        }
    }

    // epilogue: c0=(g,2t) c1=(g,2t+1) c2=(g+8,2t) c3=(g+8,2t+1) per n8-tile
    int rA = r0 + mbase + g;
    int rB = rA + 8;
#pragma unroll
    for (int j = 0; j < 6; j++) {
        int c = nbase + j * 8 + 2 * t;
        float v0 = acc[j][0], v1 = acc[j][1], v2 = acc[j][2], v3 = acc[j][3];
        if (MODE == 1) {
            float b0 = g_B2[c],  b1 = g_B2[c + 1];
            float s0 = g_BNS[c], s1 = g_BNS[c + 1];
            float t0 = g_BNT[c], t1 = g_BNT[c + 1];
            v0 = fmaxf(v0 + b0, 0.f) * s0 + t0;
            v1 = fmaxf(v1 + b1, 0.f) * s1 + t1;
            v2 = fmaxf(v2 + b0, 0.f) * s0 + t0;
            v3 = fmaxf(v3 + b1, 0.f) * s1 + t1;
        }
        if (rA < M) *(float2*)(C + (size_t)rA * 96 + c) = make_float2(v0, v1);
        if (rB < M) *(float2*)(C + (size_t)rB * 96 + c) = make_float2(v2, v3);
    }
}

// ---------------- attention logits: als/ald per node ----------------
__global__ void alsald_kernel()
{
    int n = (blockIdx.x * blockDim.x + threadIdx.x) >> 5;
    int lane = threadIdx.x & 31;
    if (n >= NN) return;
    size_t b = (size_t)n * 96;
    float v0 = g_ht[b + lane], v1 = g_ht[b + 32 + lane], v2 = g_ht[b + 64 + lane];
    float ss = v0 * g_ASRC[lane] + v1 * g_ASRC[lane + 32] + v2 * g_ASRC[lane + 64];
    float sd = v0 * g_ADST[lane] + v1 * g_ADST[lane + 32] + v2 * g_ADST[lane + 64];
#pragma unroll
    for (int off = 16; off; off >>= 1) {
        ss += __shfl_xor_sync(0xffffffffu, ss, off);
        sd += __shfl_xor_sync(0xffffffffu, sd, off);
    }
    if (lane == 0) { g_als[n] = ss; g_ald[n] = sd; }
}

// ---------------- GAT: warp per node, SINGLE fused pass, float4 gathers -------------
__global__ void gat_kernel()
{
    int n = (blockIdx.x * blockDim.x + threadIdx.x) >> 5;
    int lane = threadIdx.x & 31;
    if (n >= NN) return;
    int p0 = g_rowptr[n], p1 = g_rowptr[n + 1];
    float aldn = g_ald[n];
    float wself = __expf(lrelu(g_als[n] + aldn));

    const float4* __restrict__ ht4 = (const float4*)g_ht;
    float4 acc = make_float4(0.f, 0.f, 0.f, 0.f);
    if (lane < 24) {
        float4 v = ht4[(size_t)n * 24 + lane];
        acc.x = wself * v.x; acc.y = wself * v.y;
        acc.z = wself * v.z; acc.w = wself * v.w;
    }
    float ls = 0.f;

    for (int base = p0; base < p1; base += 32) {
        int p = base + lane;
        float wv = 0.f; int sv = 0;
        if (p < p1) {
            sv = g_col[p];
            wv = __expf(lrelu(g_als[sv] + aldn));
        }
        ls += wv;
        int cnt = min(32, p1 - base);
        for (int j = 0; j < cnt; j++) {
            float wj = __shfl_sync(0xffffffffu, wv, j);
            int   sj = __shfl_sync(0xffffffffu, sv, j);
            if (lane < 24) {
                float4 v = ht4[(size_t)sj * 24 + lane];
                acc.x += wj * v.x; acc.y += wj * v.y;
                acc.z += wj * v.z; acc.w += wj * v.w;
            }
        }
    }
#pragma unroll
    for (int o = 16; o; o >>= 1) ls += __shfl_xor_sync(0xffffffffu, ls, o);
    float inv = 1.f / (ls + wself);

    if (lane < 24) {
        float4 bb = ((const float4*)g_BG)[lane];
        float4 o;
        o.x = acc.x * inv + bb.x;
        o.y = acc.y * inv + bb.y;
        o.z = acc.z * inv + bb.z;
        o.w = acc.w * inv + bb.w;
        ((float4*)g_ao)[(size_t)n * 24 + lane] = o;
    }
}

// ---------------- global_add_pool: block per graph (batch is sorted) ----------------
template<typename T>
__device__ __forceinline__ int lbound(const T* __restrict__ a, int n, T key)
{
    int lo = 0, hi = n;
    while (lo < hi) {
        int mid = (lo + hi) >> 1;
        if (a[mid] < key) lo = mid + 1; else hi = mid;
    }
    return lo;
}

template<typename T>
__global__ void pool_kernel(const void* __restrict__ batchv)
{
    if (!type_active<T>()) return;
    const T* __restrict__ batch = (const T*)batchv;
    int g = blockIdx.x;
    int tid = threadIdx.x;        // 96 threads
    int lo = lbound<T>(batch, NN, (T)g);
    int hi = lbound<T>(batch, NN, (T)(g + 1));
    float s0 = 0.f, s1 = 0.f, s2 = 0.f, s3 = 0.f;
    int i = lo;
    for (; i + 3 < hi; i += 4) {
        s0 += g_ao[(size_t)(i + 0) * 96 + tid];
        s1 += g_ao[(size_t)(i + 1) * 96 + tid];
        s2 += g_ao[(size_t)(i + 2) * 96 + tid];
        s3 += g_ao[(size_t)(i + 3) * 96 + tid];
    }
    for (; i < hi; i++) s0 += g_ao[(size_t)i * 96 + tid];
    g_gp[g * 96 + tid] = (s0 + s1) + (s2 + s3);
}

// ---------------- fc1 + 3 heads: block per graph ----------------
__global__ void heads_kernel(const float* __restrict__ wfc, const float* __restrict__ bfc,
                             const float* __restrict__ w10, const float* __restrict__ b10,
                             const float* __restrict__ w20, const float* __restrict__ b20,
                             const float* __restrict__ w11, const float* __restrict__ b11,
                             const float* __restrict__ w21, const float* __restrict__ b21,
                             const float* __restrict__ w12, const float* __restrict__ b12,
                             const float* __restrict__ w22, const float* __restrict__ b22,
                             float* __restrict__ dout)
{
    int g = blockIdx.x;
    int tid = threadIdx.x;        // 192 threads
    __shared__ float gp[96];
    __shared__ float gf[192];
    __shared__ float hid[36];
    if (tid < 96) gp[tid] = g_gp[g * 96 + tid];
    __syncthreads();
    if (tid < FC2) {
        float acc = bfc[tid];
        for (int k = 0; k < DIMR; k++) acc += gp[k] * wfc[k * FC2 + tid];
        gf[tid] = fmaxf(acc, 0.f);
    }
    __syncthreads();
    if (tid < 36) {
        int h = tid / 12, u = tid % 12;
        const float* w1 = (h == 0) ? w10 : (h == 1) ? w11 : w12;
        const float* b1 = (h == 0) ? b10 : (h == 1) ? b11 : b12;
        float acc = b1[u];
        for (int k = 0; k < FC2; k++) acc += gf[k] * w1[k * 12 + u];
        hid[tid] = fmaxf(acc, 0.f);
    }
    __syncthreads();
    if (tid < 3) {
        const float* w2 = (tid == 0) ? w20 : (tid == 1) ? w21 : w22;
        const float* b2 = (tid == 0) ? b20 : (tid == 1) ? b21 : b22;
        float acc = b2[0];
        for (int k = 0; k < 12; k++) acc += hid[tid * 12 + k] * w2[k];
        if (tid == 0) acc = 1.f / (1.f + __expf(-acc));
        dout[g * 3 + tid] = acc;
    }
}

// ---------------- launcher (kernel launches ONLY — graph-capturable) ----------------
extern "C" void kernel_launch(void* const* d_in, const int* in_sizes, int n_in,
                              void* d_out, int out_size)
{
    const float* x     = (const float*)d_in[0];
    const void*  ei    = d_in[1];
    const void*  batch = d_in[2];
    const float* w1a = (const float*)d_in[3];
    const float* b1a = (const float*)d_in[4];
    const float* w1b = (const float*)d_in[5];
    const float* b1b = (const float*)d_in[6];
    const float* bng = (const float*)d_in[7];
    const float* bnb = (const float*)d_in[8];
    const float* bnm = (const float*)d_in[9];
    const float* bnv = (const float*)d_in[10];
    const float* wg  = (const float*)d_in[11];
    const float* bg  = (const float*)d_in[12];
    const float* asrc = (const float*)d_in[13];
    const float* adst = (const float*)d_in[14];
    const float* wfc = (const float*)d_in[15];
    const float* bfc = (const float*)d_in[16];
    const float* h0w1 = (const float*)d_in[17];
    const float* h0b1 = (const float*)d_in[18];
    const float* h0w2 = (const float*)d_in[19];
    const float* h0b2 = (const float*)d_in[20];
    const float* h1w1 = (const float*)d_in[21];
    const float* h1b1 = (const float*)d_in[22];
    const float* h1w2 = (const float*)d_in[23];
    const float* h1b2 = (const float*)d_in[24];
    const float* h2w1 = (const float*)d_in[25];
    const float* h2b1 = (const float*)d_in[26];
    const float* h2w2 = (const float*)d_in[27];
    const float* h2b2 = (const float*)d_in[28];
    float* dout = (float*)d_out;

    // dtype detect + weight prep; GEMM0 placed 4th so ncu's fixed skip profiles it
    detect_kernel<<<1, 256>>>((const int*)ei);
    prep_kernel<<<(FIN * DIMP + 255) / 256, 256>>>(w1a, b1a, w1b, b1b, bng, bnb, bnm, bnv,
                                                   wg, bg, asrc, adst);
    zero_deg_kernel<<<(NN + 255) / 256, 256>>>();
    gemm_kernel<0><<<(NN + 63) / 64, 256>>>(x);

    // CSR build
    hist_kernel<int><<<(EE + 255) / 256, 256>>>(ei);
    hist_kernel<long long><<<(EE + 255) / 256, 256>>>(ei);
    block_sum_kernel<<<NBLK, 256>>>();
    scan_partials_kernel<<<1, 128>>>();
    rowptr_kernel<<<NBLK, 256>>>();
    scatter_kernel<int><<<(EE + 255) / 256, 256>>>(ei);
    scatter_kernel<long long><<<(EE + 255) / 256, 256>>>(ei);

    // GIN: aggregate y (96-wide) with fused bias+relu, then GEMM1
    gin_agg_kernel<<<(NN * 32 + 255) / 256, 256>>>();
    gemm_kernel<1><<<(NN + 63) / 64, 256>>>(nullptr);

    // GAT: GEMM2, then als/ald, then single-pass softmax-aggregate
    gemm_kernel<2><<<(NN + 63) / 64, 256>>>(nullptr);
    alsald_kernel<<<(NN * 32 + 255) / 256, 256>>>();
    gat_kernel<<<(NN * 32 + 255) / 256, 256>>>();

    // pool + heads
    pool_kernel<int><<<GG, 96>>>(batch);
    pool_kernel<long long><<<GG, 96>>>(batch);
    heads_kernel<<<GG, 192>>>(wfc, bfc, h0w1, h0b1, h0w2, h0b2,
                              h1w1, h1b1, h1w2, h1b2, h2w1, h2b1, h2w2, h2b2, dout);
}

// round 14
// speedup vs baseline: 1.0311x; 1.0311x over previous
#include <cuda_runtime.h>
#include <math.h>
#include <stdint.h>

#define NN   100000
#define EE   3200000
#define FIN  128
#define DIMR 95
#define DIMP 96
#define GG   256
#define FC2  190
#define NEG  0.2f
#define BNEPS 1e-5f
#define NBLK 98              // ceil(NN/1024)

// ---------------- scratch (device globals; no allocation allowed) ----------------
__device__ float g_y  [(size_t)NN * DIMP];     // x @ w1a (pre-aggregation)
__device__ float g_t1 [(size_t)NN * DIMP];     // relu(y_i + sum y_j + b1a)
__device__ float g_h  [(size_t)NN * DIMP];     // BN(relu(t1@w1b+b1b))
__device__ float g_ht [(size_t)NN * DIMP];     // h@wg
__device__ float g_ao [(size_t)NN * DIMP];     // GAT out
__device__ float g_als[NN], g_ald[NN];
__device__ float g_gp [GG * DIMP];
__device__ int   g_deg[NN];
__device__ int   g_bsum[128];
__device__ int   g_boff[128];
__device__ int   g_rowptr[NN + 1];
__device__ int   g_cursor[NN];
__device__ int   g_col[EE];
__device__ float g_W1[FIN * DIMP];
__device__ float g_W2[DIMP * DIMP];
__device__ float g_W3[DIMP * DIMP];
__device__ float g_B1[DIMP], g_B2[DIMP], g_BNS[DIMP], g_BNT[DIMP];
__device__ float g_ASRC[DIMP], g_ADST[DIMP], g_BG[DIMP];
__device__ int   g_is64;    // 1 if edge_index/batch are int64, 0 if int32

__device__ __forceinline__ float lrelu(float v) { return v > 0.f ? v : NEG * v; }

// ---------------- dtype detection ----------------
// If buffer is int64 (values < 100000), every odd int32 word is 0.
__global__ void detect_kernel(const int* __restrict__ ei32)
{
    int tid = threadIdx.x;   // 256 threads
    int ok = (ei32[2 * tid + 1] == 0) ? 1 : 0;
    int cnt = __syncthreads_count(ok);
    if (tid == 0) g_is64 = (cnt == 256) ? 1 : 0;
}

template<typename T>
__device__ __forceinline__ bool type_active() { return g_is64 == (sizeof(T) == 8 ? 1 : 0); }

// ---------------- weight prep: pad everything to width 96, fold BN ----------------
__global__ void prep_kernel(const float* __restrict__ w1a, const float* __restrict__ b1a,
                            const float* __restrict__ w1b, const float* __restrict__ b1b,
                            const float* __restrict__ bng, const float* __restrict__ bnb,
                            const float* __restrict__ bnm, const float* __restrict__ bnv,
                            const float* __restrict__ wg,  const float* __restrict__ bg,
                            const float* __restrict__ asrc,const float* __restrict__ adst)
{
    int i = blockIdx.x * blockDim.x + threadIdx.x;
    if (i < FIN * DIMP) {
        int r = i / DIMP, c = i % DIMP;
        g_W1[i] = (c < DIMR) ? w1a[r * DIMR + c] : 0.f;
    }
    if (i < DIMP * DIMP) {
        int r = i / DIMP, c = i % DIMP;
        bool ok = (r < DIMR && c < DIMR);
        g_W2[i] = ok ? w1b[r * DIMR + c] : 0.f;
        g_W3[i] = ok ? wg [r * DIMR + c] : 0.f;
    }
    if (i < DIMP) {
        bool ok = i < DIMR;
        g_B1[i] = ok ? b1a[i] : 0.f;
        g_B2[i] = ok ? b1b[i] : 0.f;
        float s = ok ? bng[i] * rsqrtf(bnv[i] + BNEPS) : 0.f;
        g_BNS[i] = s;
        g_BNT[i] = ok ? (bnb[i] - bnm[i] * s) : 0.f;
        g_ASRC[i] = ok ? asrc[i] : 0.f;
        g_ADST[i] = ok ? adst[i] : 0.f;
        g_BG[i]   = ok ? bg[i]   : 0.f;
    }
}

// ---------------- CSR build (vectorized: 4 edges/thread, 16B loads) ----------------
__global__ void zero_deg_kernel()
{
    int i = blockIdx.x * blockDim.x + threadIdx.x;   // int4 stores
    if (i < NN / 4) ((int4*)g_deg)[i] = make_int4(0, 0, 0, 0);
}

template<typename T>
__global__ void hist_kernel(const void* __restrict__ eiv)
{
    if (!type_active<T>()) return;
    int e4 = (blockIdx.x * blockDim.x + threadIdx.x) * 4;
    if (e4 >= EE) return;
    int d0, d1, d2, d3;
    if (sizeof(T) == 8) {
        const longlong2* p = (const longlong2*)((const long long*)eiv + EE + e4);
        longlong2 a = p[0], b = p[1];
        d0 = (int)a.x; d1 = (int)a.y; d2 = (int)b.x; d3 = (int)b.y;
    } else {
        int4 a = *(const int4*)((const int*)eiv + EE + e4);
        d0 = a.x; d1 = a.y; d2 = a.z; d3 = a.w;
    }
    atomicAdd(&g_deg[d0], 1);
    atomicAdd(&g_deg[d1], 1);
    atomicAdd(&g_deg[d2], 1);
    atomicAdd(&g_deg[d3], 1);
}

__device__ __forceinline__ int warp_incl_scan(int v, int lane)
{
#pragma unroll
    for (int o = 1; o < 32; o <<= 1) {
        int t = __shfl_up_sync(0xffffffffu, v, o);
        if (lane >= o) v += t;
    }
    return v;
}

// per-1024-element block sums
__global__ void block_sum_kernel()
{
    int blk = blockIdx.x, tid = threadIdx.x;           // 256 threads
    int lane = tid & 31, wid = tid >> 5;
    int i0 = blk * 1024 + tid * 4;
    int s = 0;
#pragma unroll
    for (int k = 0; k < 4; k++) {
        int i = i0 + k;
        if (i < NN) s += g_deg[i];
    }
#pragma unroll
    for (int o = 16; o; o >>= 1) s += __shfl_xor_sync(0xffffffffu, s, o);
    __shared__ int ws[8];
    if (lane == 0) ws[wid] = s;
    __syncthreads();
    if (tid == 0) {
        int t = 0;
        for (int w = 0; w < 8; w++) t += ws[w];
        g_bsum[blk] = t;
    }
}

// exclusive scan of NBLK partials (1 block, 128 threads)
__global__ void scan_partials_kernel()
{
    __shared__ int sm[128];
    int tid = threadIdx.x;
    int v = (tid < NBLK) ? g_bsum[tid] : 0;
    sm[tid] = v;
    __syncthreads();
#pragma unroll
    for (int o = 1; o < 128; o <<= 1) {
        int t = (tid >= o) ? sm[tid - o] : 0;
        __syncthreads();
        sm[tid] += t;
        __syncthreads();
    }
    if (tid < NBLK) g_boff[tid] = sm[tid] - v;
}

// final rowptr: re-scan each 1024-chunk with warp shuffles + block offset
__global__ void rowptr_kernel()
{
    int blk = blockIdx.x, tid = threadIdx.x;           // 256 threads
    int lane = tid & 31, wid = tid >> 5;
    int i0 = blk * 1024 + tid * 4;
    int v[4];
#pragma unroll
    for (int k = 0; k < 4; k++) {
        int i = i0 + k;
        v[k] = (i < NN) ? g_deg[i] : 0;
    }
    int tsum = v[0] + v[1] + v[2] + v[3];
    int incl = warp_incl_scan(tsum, lane);
    __shared__ int ws[8];
    if (lane == 31) ws[wid] = incl;
    __syncthreads();
    if (wid == 0) {
        int w = (lane < 8) ? ws[lane] : 0;
        int wi = warp_incl_scan(w, lane);
        if (lane < 8) ws[lane] = wi - w;   // exclusive warp offsets
    }
    __syncthreads();
    int base = g_boff[blk] + ws[wid] + (incl - tsum);
    int pre = 0;
#pragma unroll
    for (int k = 0; k < 4; k++) {
        int i = i0 + k;
        if (i < NN) {
            int excl = base + pre;
            g_rowptr[i] = excl;
            g_cursor[i] = excl;
            if (i == NN - 1) g_rowptr[NN] = excl + v[k];
        }
        pre += v[k];
    }
}

template<typename T>
__global__ void scatter_kernel(const void* __restrict__ eiv)
{
    if (!type_active<T>()) return;
    int e4 = (blockIdx.x * blockDim.x + threadIdx.x) * 4;
    if (e4 >= EE) return;
    int s0, s1, s2, s3, d0, d1, d2, d3;
    if (sizeof(T) == 8) {
        const longlong2* ps = (const longlong2*)((const long long*)eiv + e4);
        const longlong2* pd = (const longlong2*)((const long long*)eiv + EE + e4);
        longlong2 a = ps[0], b = ps[1], c = pd[0], d = pd[1];
        s0 = (int)a.x; s1 = (int)a.y; s2 = (int)b.x; s3 = (int)b.y;
        d0 = (int)c.x; d1 = (int)c.y; d2 = (int)d.x; d3 = (int)d.y;
    } else {
        int4 a = *(const int4*)((const int*)eiv + e4);
        int4 c = *(const int4*)((const int*)eiv + EE + e4);
        s0 = a.x; s1 = a.y; s2 = a.z; s3 = a.w;
        d0 = c.x; d1 = c.y; d2 = c.z; d3 = c.w;
    }
    g_col[atomicAdd(&g_cursor[d0], 1)] = s0;
    g_col[atomicAdd(&g_cursor[d1], 1)] = s1;
    g_col[atomicAdd(&g_cursor[d2], 1)] = s2;
    g_col[atomicAdd(&g_cursor[d3], 1)] = s3;
}

// ---------------- GIN aggregation (96-wide, post-GEMM): warp per node, float4 ------
// t1 = relu( y_i + sum_{j->i} y_j + b1a );  lanes 0..23 each own 4 contiguous cols
__global__ void gin_agg_kernel()
{
    int n = (blockIdx.x * blockDim.x + threadIdx.x) >> 5;
    int lane = threadIdx.x & 31;
    if (n >= NN) return;
    int p0 = g_rowptr[n], p1 = g_rowptr[n + 1];
    const float4* __restrict__ y4 = (const float4*)g_y;
    if (lane < 24) {
        float4 acc = y4[(size_t)n * 24 + lane];
        for (int p = p0; p < p1; p++) {
            int s = g_col[p];
            float4 v = y4[(size_t)s * 24 + lane];
            acc.x += v.x; acc.y += v.y; acc.z += v.z; acc.w += v.w;
        }
        float4 bb = ((const float4*)g_B1)[lane];
        float4 o;
        o.x = fmaxf(acc.x + bb.x, 0.f);
        o.y = fmaxf(acc.y + bb.y, 0.f);
        o.z = fmaxf(acc.z + bb.z, 0.f);
        o.w = fmaxf(acc.w + bb.w, 0.f);
        ((float4*)g_t1)[(size_t)n * 24 + lane] = o;
    }
}

// ---------------- tiled GEMM (double-buffered, FFMA2 packed math) ----------------
// BM=64, BN=96, BK=16, 256 threads; thread = 8 rows (4 packed pairs) x 3 cols.
// Inner loop uses fma.rn.f32x2: one instruction = 2 FMAs. A pairs load as
// ld.shared.v2.u64 (warp-broadcast); B scalars stride-3 conflict-free, duplicated
// via mov.b64. ONE __syncthreads per tile (double buffer).
// MODE 0: A=x(ext) K=128 W=g_W1 C=g_y  epi=plain
// MODE 1: A=g_t1   K=96  W=g_W2 C=g_h  epi=BN(relu+bias)
// MODE 2: A=g_h    K=96  W=g_W3 C=g_ht epi=plain + fused als/ald
template<int MODE>
__global__ __launch_bounds__(256, 4)
void gemm_kernel(const float* __restrict__ Aext)
{
    const float* __restrict__ A = (MODE == 0) ? Aext : (MODE == 1) ? g_t1 : g_h;
    const float* __restrict__ W = (MODE == 0) ? g_W1 : (MODE == 1) ? g_W2 : g_W3;
    float* __restrict__ C       = (MODE == 0) ? g_y  : (MODE == 1) ? g_h  : g_ht;
    const int K = (MODE == 0) ? FIN : DIMP;
    const int M = NN;

    __shared__ __align__(16) float As[2][16][68];  // k-major, 68 pad (row 272B, 16B-mult)
    __shared__ __align__(16) float Bs[2][16][96];
    int tid = threadIdx.x;
    int ty = tid >> 5;              // warp id 0..7 -> 8-row slab
    int lane = tid & 31;            // -> 3 cols
    int r0 = blockIdx.x * 64;

    // A-load geometry: 64x16 tile = 256 float4, exactly 1 per thread
    const int arow = tid >> 2, akq = tid & 3;
    const int gra = r0 + arow;
    // B-load geometry: 384 float4; tid and tid+256 (valid if <384)
    const int brow0 = tid / 24,  bc0 = tid % 24;
    const bool bv1 = (tid + 256) < 384;
    const int brow1 = (tid + 256) / 24, bc1 = (tid + 256) % 24;

    float4 pa, pb0, pb1;
    const float4 z4 = make_float4(0.f, 0.f, 0.f, 0.f);

    // prefetch tile 0
    pa  = (gra < M) ? *(const float4*)(A + (size_t)gra * K + akq * 4) : z4;
    pb0 = *(const float4*)(W + (size_t)brow0 * 96 + bc0 * 4);
    pb1 = bv1 ? *(const float4*)(W + (size_t)brow1 * 96 + bc1 * 4) : z4;

    // store tile 0 -> buffer 0
    As[0][akq * 4 + 0][arow] = pa.x;
    As[0][akq * 4 + 1][arow] = pa.y;
    As[0][akq * 4 + 2][arow] = pa.z;
    As[0][akq * 4 + 3][arow] = pa.w;
    *(float4*)(&Bs[0][brow0][bc0 * 4]) = pb0;
    if (bv1) *(float4*)(&Bs[0][brow1][bc1 * 4]) = pb1;
    __syncthreads();

    unsigned long long acc2[4][3];   // packed f32x2 accumulators: rows (2i, 2i+1)
#pragma unroll
    for (int i = 0; i < 4; i++)
#pragma unroll
        for (int j = 0; j < 3; j++) acc2[i][j] = 0ULL;

    const unsigned as_shb = (unsigned)__cvta_generic_to_shared(&As[0][0][0]) + ty * 32;

    const int ntile = K >> 4;
#pragma unroll 1
    for (int kt = 0; kt < ntile; kt++) {
        int cur = kt & 1, nxt = cur ^ 1;
        bool more = (kt + 1) < ntile;
        if (more) {
            int kb = (kt + 1) * 16;
            pa  = (gra < M) ? *(const float4*)(A + (size_t)gra * K + kb + akq * 4) : z4;
            pb0 = *(const float4*)(W + (size_t)(kb + brow0) * 96 + bc0 * 4);
            pb1 = bv1 ? *(const float4*)(W + (size_t)(kb + brow1) * 96 + bc1 * 4) : z4;
        }
        unsigned abase = as_shb + (unsigned)cur * (16 * 68 * 4);
#pragma unroll
        for (int kk = 0; kk < 16; kk++) {
            unsigned long long a2[4];
            asm volatile("ld.shared.v2.u64 {%0, %1}, [%2];"
                         : "=l"(a2[0]), "=l"(a2[1]) : "r"(abase + kk * 272));
            asm volatile("ld.shared.v2.u64 {%0, %1}, [%2];"
                         : "=l"(a2[2]), "=l"(a2[3]) : "r"(abase + kk * 272 + 16));
            float b0 = Bs[cur][kk][lane * 3 + 0];
            float b1 = Bs[cur][kk][lane * 3 + 1];
            float b2 = Bs[cur][kk][lane * 3 + 2];
            unsigned long long bb0, bb1, bb2;
            asm("mov.b64 %0, {%1, %1};" : "=l"(bb0) : "r"(__float_as_uint(b0)));
            asm("mov.b64 %0, {%1, %1};" : "=l"(bb1) : "r"(__float_as_uint(b1)));
            asm("mov.b64 %0, {%1, %1};" : "=l"(bb2) : "r"(__float_as_uint(b2)));
#pragma unroll
            for (int i = 0; i < 4; i++) {
                asm("fma.rn.f32x2 %0, %1, %2, %0;" : "+l"(acc2[i][0]) : "l"(a2[i]), "l"(bb0));
                asm("fma.rn.f32x2 %0, %1, %2, %0;" : "+l"(acc2[i][1]) : "l"(a2[i]), "l"(bb1));
                asm("fma.rn.f32x2 %0, %1, %2, %0;" : "+l"(acc2[i][2]) : "l"(a2[i]), "l"(bb2));
            }
        }
        if (more) {
            As[nxt][akq * 4 + 0][arow] = pa.x;
            As[nxt][akq * 4 + 1][arow] = pa.y;
            As[nxt][akq * 4 + 2][arow] = pa.z;
            As[nxt][akq * 4 + 3][arow] = pa.w;
            *(float4*)(&Bs[nxt][brow0][bc0 * 4]) = pb0;
            if (bv1) *(float4*)(&Bs[nxt][brow1][bc1 * 4]) = pb1;
            __syncthreads();
        }
    }

    // unpack accumulators to scalar rows
    float acc[8][3];
#pragma unroll
    for (int i = 0; i < 4; i++)
#pragma unroll
        for (int j = 0; j < 3; j++) {
            unsigned lo, hi;
            asm("mov.b64 {%0, %1}, %2;" : "=r"(lo), "=r"(hi) : "l"(acc2[i][j]));
            acc[2 * i + 0][j] = __uint_as_float(lo);
            acc[2 * i + 1][j] = __uint_as_float(hi);
        }

#pragma unroll
    for (int j = 0; j < 3; j++) {
        int c = lane * 3 + j;
        float bi = (MODE == 1) ? g_B2[c] : 0.f;
        float sc = (MODE == 1) ? g_BNS[c] : 1.f;
        float sh = (MODE == 1) ? g_BNT[c] : 0.f;
#pragma unroll
        for (int i = 0; i < 8; i++) {
            int gr = r0 + ty * 8 + i;
            if (gr < M) {
                float v = acc[i][j];
                if (MODE == 1) v = fmaxf(v + bi, 0.f) * sc + sh;
                C[(size_t)gr * 96 + c] = v;
            }
        }
    }

    if (MODE == 2) {
        // fused als/ald: warp-reduce acc rows against a_src / a_dst
        float asr0 = g_ASRC[lane * 3 + 0], asr1 = g_ASRC[lane * 3 + 1], asr2 = g_ASRC[lane * 3 + 2];
        float ads0 = g_ADST[lane * 3 + 0], ads1 = g_ADST[lane * 3 + 1], ads2 = g_ADST[lane * 3 + 2];
#pragma unroll
        for (int i = 0; i < 8; i++) {
            float ps = acc[i][0] * asr0 + acc[i][1] * asr1 + acc[i][2] * asr2;
            float pd = acc[i][0] * ads0 + acc[i][1] * ads1 + acc[i][2] * ads2;
#pragma unroll
            for (int o = 16; o; o >>= 1) {
                ps += __shfl_xor_sync(0xffffffffu, ps, o);
                pd += __shfl_xor_sync(0xffffffffu, pd, o);
            }
            int gr = r0 + ty * 8 + i;
            if (lane == 0 && gr < M) { g_als[gr] = ps; g_ald[gr] = pd; }
        }
    }
}

// ---------------- GAT: warp per node, SINGLE fused pass, float4 gathers -------------
__global__ void gat_kernel()
{
    int n = (blockIdx.x * blockDim.x + threadIdx.x) >> 5;
    int lane = threadIdx.x & 31;
    if (n >= NN) return;
    int p0 = g_rowptr[n], p1 = g_rowptr[n + 1];
    float aldn = g_ald[n];
    float wself = __expf(lrelu(g_als[n] + aldn));

    const float4* __restrict__ ht4 = (const float4*)g_ht;
    float4 acc = make_float4(0.f, 0.f, 0.f, 0.f);
    if (lane < 24) {
        float4 v = ht4[(size_t)n * 24 + lane];
        acc.x = wself * v.x; acc.y = wself * v.y;
        acc.z = wself * v.z; acc.w = wself * v.w;
    }
    float ls = 0.f;

    for (int base = p0; base < p1; base += 32) {
        int p = base + lane;
        float wv = 0.f; int sv = 0;
        if (p < p1) {
            sv = g_col[p];
            wv = __expf(lrelu(g_als[sv] + aldn));
        }
        ls += wv;
        int cnt = min(32, p1 - base);
        for (int j = 0; j < cnt; j++) {
            float wj = __shfl_sync(0xffffffffu, wv, j);
            int   sj = __shfl_sync(0xffffffffu, sv, j);
            if (lane < 24) {
                float4 v = ht4[(size_t)sj * 24 + lane];
                acc.x += wj * v.x; acc.y += wj * v.y;
                acc.z += wj * v.z; acc.w += wj * v.w;
            }
        }
    }
#pragma unroll
    for (int o = 16; o; o >>= 1) ls += __shfl_xor_sync(0xffffffffu, ls, o);
    float inv = 1.f / (ls + wself);

    if (lane < 24) {
        float4 bb = ((const float4*)g_BG)[lane];
        float4 o;
        o.x = acc.x * inv + bb.x;
        o.y = acc.y * inv + bb.y;
        o.z = acc.z * inv + bb.z;
        o.w = acc.w * inv + bb.w;
        ((float4*)g_ao)[(size_t)n * 24 + lane] = o;
    }
}

// ---------------- global_add_pool: block per graph (batch is sorted) ----------------
template<typename T>
__device__ __forceinline__ int lbound(const T* __restrict__ a, int n, T key)
{
    int lo = 0, hi = n;
    while (lo < hi) {
        int mid = (lo + hi) >> 1;
        if (a[mid] < key) lo = mid + 1; else hi = mid;
    }
    return lo;
}

template<typename T>
__global__ void pool_kernel(const void* __restrict__ batchv)
{
    if (!type_active<T>()) return;
    const T* __restrict__ batch = (const T*)batchv;
    int g = blockIdx.x;
    int tid = threadIdx.x;        // 96 threads
    int lo = lbound<T>(batch, NN, (T)g);
    int hi = lbound<T>(batch, NN, (T)(g + 1));
    float s0 = 0.f, s1 = 0.f, s2 = 0.f, s3 = 0.f;
    int i = lo;
    for (; i + 3 < hi; i += 4) {
        s0 += g_ao[(size_t)(i + 0) * 96 + tid];
        s1 += g_ao[(size_t)(i + 1) * 96 + tid];
        s2 += g_ao[(size_t)(i + 2) * 96 + tid];
        s3 += g_ao[(size_t)(i + 3) * 96 + tid];
    }
    for (; i < hi; i++) s0 += g_ao[(size_t)i * 96 + tid];
    g_gp[g * 96 + tid] = (s0 + s1) + (s2 + s3);
}

// ---------------- fc1 + 3 heads: block per graph ----------------
__global__ void heads_kernel(const float* __restrict__ wfc, const float* __restrict__ bfc,
                             const float* __restrict__ w10, const float* __restrict__ b10,
                             const float* __restrict__ w20, const float* __restrict__ b20,
                             const float* __restrict__ w11, const float* __restrict__ b11,
                             const float* __restrict__ w21, const float* __restrict__ b21,
                             const float* __restrict__ w12, const float* __restrict__ b12,
                             const float* __restrict__ w22, const float* __restrict__ b22,
                             float* __restrict__ dout)
{
    int g = blockIdx.x;
    int tid = threadIdx.x;        // 192 threads
    __shared__ float gp[96];
    __shared__ float gf[192];
    __shared__ float hid[36];
    if (tid < 96) gp[tid] = g_gp[g * 96 + tid];
    __syncthreads();
    if (tid < FC2) {
        float acc = bfc[tid];
        for (int k = 0; k < DIMR; k++) acc += gp[k] * wfc[k * FC2 + tid];
        gf[tid] = fmaxf(acc, 0.f);
    }
    __syncthreads();
    if (tid < 36) {
        int h = tid / 12, u = tid % 12;
        const float* w1 = (h == 0) ? w10 : (h == 1) ? w11 : w12;
        const float* b1 = (h == 0) ? b10 : (h == 1) ? b11 : b12;
        float acc = b1[u];
        for (int k = 0; k < FC2; k++) acc += gf[k] * w1[k * 12 + u];
        hid[tid] = fmaxf(acc, 0.f);
    }
    __syncthreads();
    if (tid < 3) {
        const float* w2 = (tid == 0) ? w20 : (tid == 1) ? w21 : w22;
        const float* b2 = (tid == 0) ? b20 : (tid == 1) ? b21 : b22;
        float acc = b2[0];
        for (int k = 0; k < 12; k++) acc += hid[tid * 12 + k] * w2[k];
        if (tid == 0) acc = 1.f / (1.f + __expf(-acc));
        dout[g * 3 + tid] = acc;
    }
}

// ---------------- launcher (kernel launches ONLY — graph-capturable) ----------------
extern "C" void kernel_launch(void* const* d_in, const int* in_sizes, int n_in,
                              void* d_out, int out_size)
{
    const float* x     = (const float*)d_in[0];
    const void*  ei    = d_in[1];
    const void*  batch = d_in[2];
    const float* w1a = (const float*)d_in[3];
    const float* b1a = (const float*)d_in[4];
    const float* w1b = (const float*)d_in[5];
    const float* b1b = (const float*)d_in[6];
    const float* bng = (const float*)d_in[7];
    const float* bnb = (const float*)d_in[8];
    const float* bnm = (const float*)d_in[9];
    const float* bnv = (const float*)d_in[10];
    const float* wg  = (const float*)d_in[11];
    const float* bg  = (const float*)d_in[12];
    const float* asrc = (const float*)d_in[13];
    const float* adst = (const float*)d_in[14];
    const float* wfc = (const float*)d_in[15];
    const float* bfc = (const float*)d_in[16];
    const float* h0w1 = (const float*)d_in[17];
    const float* h0b1 = (const float*)d_in[18];
    const float* h0w2 = (const float*)d_in[19];
    const float* h0b2 = (const float*)d_in[20];
    const float* h1w1 = (const float*)d_in[21];
    const float* h1b1 = (const float*)d_in[22];
    const float* h1w2 = (const float*)d_in[23];
    const float* h1b2 = (const float*)d_in[24];
    const float* h2w1 = (const float*)d_in[25];
    const float* h2b1 = (const float*)d_in[26];
    const float* h2w2 = (const float*)d_in[27];
    const float* h2b2 = (const float*)d_in[28];
    float* dout = (float*)d_out;

    // dtype detect + weight prep; GEMM0 placed 4th so ncu's fixed skip profiles it
    detect_kernel<<<1, 256>>>((const int*)ei);
    prep_kernel<<<(FIN * DIMP + 255) / 256, 256>>>(w1a, b1a, w1b, b1b, bng, bnb, bnm, bnv,
                                                   wg, bg, asrc, adst);
    zero_deg_kernel<<<(NN / 4 + 255) / 256, 256>>>();
    gemm_kernel<0><<<(NN + 63) / 64, 256>>>(x);

    // CSR build (4 edges per thread)
    hist_kernel<int><<<(EE / 4 + 255) / 256, 256>>>(ei);
    hist_kernel<long long><<<(EE / 4 + 255) / 256, 256>>>(ei);
    block_sum_kernel<<<NBLK, 256>>>();
    scan_partials_kernel<<<1, 128>>>();
    rowptr_kernel<<<NBLK, 256>>>();
    scatter_kernel<int><<<(EE / 4 + 255) / 256, 256>>>(ei);
    scatter_kernel<long long><<<(EE / 4 + 255) / 256, 256>>>(ei);

    // GIN: aggregate y (96-wide) with fused bias+relu, then GEMM1
    gin_agg_kernel<<<(NN * 32 + 255) / 256, 256>>>();
    gemm_kernel<1><<<(NN + 63) / 64, 256>>>(nullptr);

    // GAT: GEMM2 (+fused als/ald), then single-pass softmax-aggregate
    gemm_kernel<2><<<(NN + 63) / 64, 256>>>(nullptr);
    gat_kernel<<<(NN * 32 + 255) / 256, 256>>>();

    // pool + heads
    pool_kernel<int><<<GG, 96>>>(batch);
    pool_kernel<long long><<<GG, 96>>>(batch);
    heads_kernel<<<GG, 192>>>(wfc, bfc, h0w1, h0b1, h0w2, h0b2,
                              h1w1, h1b1, h1w2, h1b2, h2w1, h2b1, h2w2, h2b2, dout);
}

// round 15
// speedup vs baseline: 1.1180x; 1.0843x over previous
#include <cuda_runtime.h>
#include <cuda_fp16.h>
#include <math.h>
#include <stdint.h>

#define NN   100000
#define EE   3200000
#define FIN  128
#define DIMR 95
#define DIMP 96
#define GG   256
#define FC2  190
#define NEG  0.2f
#define BNEPS 1e-5f
#define NBLK 98              // ceil(NN/1024)

// ---------------- scratch (device globals; no allocation allowed) ----------------
__device__ __half g_yh [(size_t)NN * DIMP];    // x @ w1a, fp16 (gather table)
__device__ float  g_t1 [(size_t)NN * DIMP];    // relu(y_i + sum y_j + b1a)
__device__ float  g_h  [(size_t)NN * DIMP];    // BN(relu(t1@w1b+b1b))
__device__ __half g_hth[(size_t)NN * DIMP];    // h@wg, fp16 (gather table)
__device__ float  g_ao [(size_t)NN * DIMP];    // GAT out
__device__ float  g_als[NN], g_ald[NN];
__device__ float  g_gp [GG * DIMP];
__device__ int    g_deg[NN];
__device__ int    g_bsum[128];
__device__ int    g_boff[128];
__device__ int    g_rowptr[NN + 1];
__device__ int    g_cursor[NN];
__device__ int    g_col[EE];
__device__ float  g_W1[FIN * DIMP];
__device__ float  g_W2[DIMP * DIMP];
__device__ float  g_W3[DIMP * DIMP];
__device__ float  g_B1[DIMP], g_B2[DIMP], g_BNS[DIMP], g_BNT[DIMP];
__device__ float  g_ASRC[DIMP], g_ADST[DIMP], g_BG[DIMP];
__device__ int    g_is64;   // 1 if edge_index/batch are int64, 0 if int32

__device__ __forceinline__ float lrelu(float v) { return v > 0.f ? v : NEG * v; }

// load 4 fp16 cols (8B) and convert to float4
__device__ __forceinline__ float4 ldh4(const __half* p)
{
    uint2 u = *(const uint2*)p;
    __half2 h0 = *(__half2*)&u.x, h1 = *(__half2*)&u.y;
    float2 f0 = __half22float2(h0), f1 = __half22float2(h1);
    return make_float4(f0.x, f0.y, f1.x, f1.y);
}

// ---------------- dtype detection ----------------
__global__ void detect_kernel(const int* __restrict__ ei32)
{
    int tid = threadIdx.x;   // 256 threads
    int ok = (ei32[2 * tid + 1] == 0) ? 1 : 0;
    int cnt = __syncthreads_count(ok);
    if (tid == 0) g_is64 = (cnt == 256) ? 1 : 0;
}

template<typename T>
__device__ __forceinline__ bool type_active() { return g_is64 == (sizeof(T) == 8 ? 1 : 0); }

// ---------------- weight prep: pad everything to width 96, fold BN ----------------
__global__ void prep_kernel(const float* __restrict__ w1a, const float* __restrict__ b1a,
                            const float* __restrict__ w1b, const float* __restrict__ b1b,
                            const float* __restrict__ bng, const float* __restrict__ bnb,
                            const float* __restrict__ bnm, const float* __restrict__ bnv,
                            const float* __restrict__ wg,  const float* __restrict__ bg,
                            const float* __restrict__ asrc,const float* __restrict__ adst)
{
    int i = blockIdx.x * blockDim.x + threadIdx.x;
    if (i < FIN * DIMP) {
        int r = i / DIMP, c = i % DIMP;
        g_W1[i] = (c < DIMR) ? w1a[r * DIMR + c] : 0.f;
    }
    if (i < DIMP * DIMP) {
        int r = i / DIMP, c = i % DIMP;
        bool ok = (r < DIMR && c < DIMR);
        g_W2[i] = ok ? w1b[r * DIMR + c] : 0.f;
        g_W3[i] = ok ? wg [r * DIMR + c] : 0.f;
    }
    if (i < DIMP) {
        bool ok = i < DIMR;
        g_B1[i] = ok ? b1a[i] : 0.f;
        g_B2[i] = ok ? b1b[i] : 0.f;
        float s = ok ? bng[i] * rsqrtf(bnv[i] + BNEPS) : 0.f;
        g_BNS[i] = s;
        g_BNT[i] = ok ? (bnb[i] - bnm[i] * s) : 0.f;
        g_ASRC[i] = ok ? asrc[i] : 0.f;
        g_ADST[i] = ok ? adst[i] : 0.f;
        g_BG[i]   = ok ? bg[i]   : 0.f;
    }
}

// ---------------- CSR build (vectorized: 4 edges/thread, 16B loads) ----------------
__global__ void zero_deg_kernel()
{
    int i = blockIdx.x * blockDim.x + threadIdx.x;   // int4 stores
    if (i < NN / 4) ((int4*)g_deg)[i] = make_int4(0, 0, 0, 0);
}

template<typename T>
__global__ void hist_kernel(const void* __restrict__ eiv)
{
    if (!type_active<T>()) return;
    int e4 = (blockIdx.x * blockDim.x + threadIdx.x) * 4;
    if (e4 >= EE) return;
    int d0, d1, d2, d3;
    if (sizeof(T) == 8) {
        const longlong2* p = (const longlong2*)((const long long*)eiv + EE + e4);
        longlong2 a = p[0], b = p[1];
        d0 = (int)a.x; d1 = (int)a.y; d2 = (int)b.x; d3 = (int)b.y;
    } else {
        int4 a = *(const int4*)((const int*)eiv + EE + e4);
        d0 = a.x; d1 = a.y; d2 = a.z; d3 = a.w;
    }
    atomicAdd(&g_deg[d0], 1);
    atomicAdd(&g_deg[d1], 1);
    atomicAdd(&g_deg[d2], 1);
    atomicAdd(&g_deg[d3], 1);
}

__device__ __forceinline__ int warp_incl_scan(int v, int lane)
{
#pragma unroll
    for (int o = 1; o < 32; o <<= 1) {
        int t = __shfl_up_sync(0xffffffffu, v, o);
        if (lane >= o) v += t;
    }
    return v;
}

__global__ void block_sum_kernel()
{
    int blk = blockIdx.x, tid = threadIdx.x;           // 256 threads
    int lane = tid & 31, wid = tid >> 5;
    int i0 = blk * 1024 + tid * 4;
    int s = 0;
#pragma unroll
    for (int k = 0; k < 4; k++) {
        int i = i0 + k;
        if (i < NN) s += g_deg[i];
    }
#pragma unroll
    for (int o = 16; o; o >>= 1) s += __shfl_xor_sync(0xffffffffu, s, o);
    __shared__ int ws[8];
    if (lane == 0) ws[wid] = s;
    __syncthreads();
    if (tid == 0) {
        int t = 0;
        for (int w = 0; w < 8; w++) t += ws[w];
        g_bsum[blk] = t;
    }
}

__global__ void scan_partials_kernel()
{
    __shared__ int sm[128];
    int tid = threadIdx.x;
    int v = (tid < NBLK) ? g_bsum[tid] : 0;
    sm[tid] = v;
    __syncthreads();
#pragma unroll
    for (int o = 1; o < 128; o <<= 1) {
        int t = (tid >= o) ? sm[tid - o] : 0;
        __syncthreads();
        sm[tid] += t;
        __syncthreads();
    }
    if (tid < NBLK) g_boff[tid] = sm[tid] - v;
}

__global__ void rowptr_kernel()
{
    int blk = blockIdx.x, tid = threadIdx.x;           // 256 threads
    int lane = tid & 31, wid = tid >> 5;
    int i0 = blk * 1024 + tid * 4;
    int v[4];
#pragma unroll
    for (int k = 0; k < 4; k++) {
        int i = i0 + k;
        v[k] = (i < NN) ? g_deg[i] : 0;
    }
    int tsum = v[0] + v[1] + v[2] + v[3];
    int incl = warp_incl_scan(tsum, lane);
    __shared__ int ws[8];
    if (lane == 31) ws[wid] = incl;
    __syncthreads();
    if (wid == 0) {
        int w = (lane < 8) ? ws[lane] : 0;
        int wi = warp_incl_scan(w, lane);
        if (lane < 8) ws[lane] = wi - w;   // exclusive warp offsets
    }
    __syncthreads();
    int base = g_boff[blk] + ws[wid] + (incl - tsum);
    int pre = 0;
#pragma unroll
    for (int k = 0; k < 4; k++) {
        int i = i0 + k;
        if (i < NN) {
            int excl = base + pre;
            g_rowptr[i] = excl;
            g_cursor[i] = excl;
            if (i == NN - 1) g_rowptr[NN] = excl + v[k];
        }
        pre += v[k];
    }
}

template<typename T>
__global__ void scatter_kernel(const void* __restrict__ eiv)
{
    if (!type_active<T>()) return;
    int e4 = (blockIdx.x * blockDim.x + threadIdx.x) * 4;
    if (e4 >= EE) return;
    int s0, s1, s2, s3, d0, d1, d2, d3;
    if (sizeof(T) == 8) {
        const longlong2* ps = (const longlong2*)((const long long*)eiv + e4);
        const longlong2* pd = (const longlong2*)((const long long*)eiv + EE + e4);
        longlong2 a = ps[0], b = ps[1], c = pd[0], d = pd[1];
        s0 = (int)a.x; s1 = (int)a.y; s2 = (int)b.x; s3 = (int)b.y;
        d0 = (int)c.x; d1 = (int)c.y; d2 = (int)d.x; d3 = (int)d.y;
    } else {
        int4 a = *(const int4*)((const int*)eiv + e4);
        int4 c = *(const int4*)((const int*)eiv + EE + e4);
        s0 = a.x; s1 = a.y; s2 = a.z; s3 = a.w;
        d0 = c.x; d1 = c.y; d2 = c.z; d3 = c.w;
    }
    g_col[atomicAdd(&g_cursor[d0], 1)] = s0;
    g_col[atomicAdd(&g_cursor[d1], 1)] = s1;
    g_col[atomicAdd(&g_cursor[d2], 1)] = s2;
    g_col[atomicAdd(&g_cursor[d3], 1)] = s3;
}

// ---------------- GIN aggregation: warp per node, fp16 gathers, fp32 accumulate ----
// t1 = relu( y_i + sum_{j->i} y_j + b1a );  lanes 0..23 each own 4 contiguous cols
__global__ void gin_agg_kernel()
{
    int n = (blockIdx.x * blockDim.x + threadIdx.x) >> 5;
    int lane = threadIdx.x & 31;
    if (n >= NN) return;
    int p0 = g_rowptr[n], p1 = g_rowptr[n + 1];
    if (lane < 24) {
        float4 acc = ldh4(g_yh + (size_t)n * 96 + lane * 4);
        for (int p = p0; p < p1; p++) {
            int s = g_col[p];
            float4 v = ldh4(g_yh + (size_t)s * 96 + lane * 4);
            acc.x += v.x; acc.y += v.y; acc.z += v.z; acc.w += v.w;
        }
        float4 bb = ((const float4*)g_B1)[lane];
        float4 o;
        o.x = fmaxf(acc.x + bb.x, 0.f);
        o.y = fmaxf(acc.y + bb.y, 0.f);
        o.z = fmaxf(acc.z + bb.z, 0.f);
        o.w = fmaxf(acc.w + bb.w, 0.f);
        ((float4*)g_t1)[(size_t)n * 24 + lane] = o;
    }
}

// ---------------- tiled GEMM (double-buffered, FFMA2 packed math) ----------------
// BM=64, BN=96, BK=16, 256 threads; thread = 8 rows (4 packed pairs) x 3 cols.
// MODE 0: A=x(ext) K=128 W=g_W1 C=g_yh  (fp16 out)
// MODE 1: A=g_t1   K=96  W=g_W2 C=g_h   epi=BN(relu+bias), fp32 out
// MODE 2: A=g_h    K=96  W=g_W3 C=g_hth (fp16 out) + fused als/ald (fp32 accs)
template<int MODE>
__global__ __launch_bounds__(256, 4)
void gemm_kernel(const float* __restrict__ Aext)
{
    const float* __restrict__ A = (MODE == 0) ? Aext : (MODE == 1) ? g_t1 : g_h;
    const float* __restrict__ W = (MODE == 0) ? g_W1 : (MODE == 1) ? g_W2 : g_W3;
    const int K = (MODE == 0) ? FIN : DIMP;
    const int M = NN;

    __shared__ __align__(16) float As[2][16][68];  // k-major, 68 pad (row 272B)
    __shared__ __align__(16) float Bs[2][16][96];
    int tid = threadIdx.x;
    int ty = tid >> 5;              // warp id 0..7 -> 8-row slab
    int lane = tid & 31;            // -> 3 cols
    int r0 = blockIdx.x * 64;

    const int arow = tid >> 2, akq = tid & 3;
    const int gra = r0 + arow;
    const int brow0 = tid / 24,  bc0 = tid % 24;
    const bool bv1 = (tid + 256) < 384;
    const int brow1 = (tid + 256) / 24, bc1 = (tid + 256) % 24;

    float4 pa, pb0, pb1;
    const float4 z4 = make_float4(0.f, 0.f, 0.f, 0.f);

    pa  = (gra < M) ? *(const float4*)(A + (size_t)gra * K + akq * 4) : z4;
    pb0 = *(const float4*)(W + (size_t)brow0 * 96 + bc0 * 4);
    pb1 = bv1 ? *(const float4*)(W + (size_t)brow1 * 96 + bc1 * 4) : z4;

    As[0][akq * 4 + 0][arow] = pa.x;
    As[0][akq * 4 + 1][arow] = pa.y;
    As[0][akq * 4 + 2][arow] = pa.z;
    As[0][akq * 4 + 3][arow] = pa.w;
    *(float4*)(&Bs[0][brow0][bc0 * 4]) = pb0;
    if (bv1) *(float4*)(&Bs[0][brow1][bc1 * 4]) = pb1;
    __syncthreads();

    unsigned long long acc2[4][3];   // packed f32x2 accumulators: rows (2i, 2i+1)
#pragma unroll
    for (int i = 0; i < 4; i++)
#pragma unroll
        for (int j = 0; j < 3; j++) acc2[i][j] = 0ULL;

    const unsigned as_shb = (unsigned)__cvta_generic_to_shared(&As[0][0][0]) + ty * 32;

    const int ntile = K >> 4;
#pragma unroll 1
    for (int kt = 0; kt < ntile; kt++) {
        int cur = kt & 1, nxt = cur ^ 1;
        bool more = (kt + 1) < ntile;
        if (more) {
            int kb = (kt + 1) * 16;
            pa  = (gra < M) ? *(const float4*)(A + (size_t)gra * K + kb + akq * 4) : z4;
            pb0 = *(const float4*)(W + (size_t)(kb + brow0) * 96 + bc0 * 4);
            pb1 = bv1 ? *(const float4*)(W + (size_t)(kb + brow1) * 96 + bc1 * 4) : z4;
        }
        unsigned abase = as_shb + (unsigned)cur * (16 * 68 * 4);
#pragma unroll
        for (int kk = 0; kk < 16; kk++) {
            unsigned long long a2[4];
            asm volatile("ld.shared.v2.u64 {%0, %1}, [%2];"
                         : "=l"(a2[0]), "=l"(a2[1]) : "r"(abase + kk * 272));
            asm volatile("ld.shared.v2.u64 {%0, %1}, [%2];"
                         : "=l"(a2[2]), "=l"(a2[3]) : "r"(abase + kk * 272 + 16));
            float b0 = Bs[cur][kk][lane * 3 + 0];
            float b1 = Bs[cur][kk][lane * 3 + 1];
            float b2 = Bs[cur][kk][lane * 3 + 2];
            unsigned long long bb0, bb1, bb2;
            asm("mov.b64 %0, {%1, %1};" : "=l"(bb0) : "r"(__float_as_uint(b0)));
            asm("mov.b64 %0, {%1, %1};" : "=l"(bb1) : "r"(__float_as_uint(b1)));
            asm("mov.b64 %0, {%1, %1};" : "=l"(bb2) : "r"(__float_as_uint(b2)));
#pragma unroll
            for (int i = 0; i < 4; i++) {
                asm("fma.rn.f32x2 %0, %1, %2, %0;" : "+l"(acc2[i][0]) : "l"(a2[i]), "l"(bb0));
                asm("fma.rn.f32x2 %0, %1, %2, %0;" : "+l"(acc2[i][1]) : "l"(a2[i]), "l"(bb1));
                asm("fma.rn.f32x2 %0, %1, %2, %0;" : "+l"(acc2[i][2]) : "l"(a2[i]), "l"(bb2));
            }
        }
        if (more) {
            As[nxt][akq * 4 + 0][arow] = pa.x;
            As[nxt][akq * 4 + 1][arow] = pa.y;
            As[nxt][akq * 4 + 2][arow] = pa.z;
            As[nxt][akq * 4 + 3][arow] = pa.w;
            *(float4*)(&Bs[nxt][brow0][bc0 * 4]) = pb0;
            if (bv1) *(float4*)(&Bs[nxt][brow1][bc1 * 4]) = pb1;
            __syncthreads();
        }
    }

    // unpack accumulators to scalar rows
    float acc[8][3];
#pragma unroll
    for (int i = 0; i < 4; i++)
#pragma unroll
        for (int j = 0; j < 3; j++) {
            unsigned lo, hi;
            asm("mov.b64 {%0, %1}, %2;" : "=r"(lo), "=r"(hi) : "l"(acc2[i][j]));
            acc[2 * i + 0][j] = __uint_as_float(lo);
            acc[2 * i + 1][j] = __uint_as_float(hi);
        }

#pragma unroll
    for (int j = 0; j < 3; j++) {
        int c = lane * 3 + j;
        float bi = (MODE == 1) ? g_B2[c] : 0.f;
        float sc = (MODE == 1) ? g_BNS[c] : 1.f;
        float sh = (MODE == 1) ? g_BNT[c] : 0.f;
#pragma unroll
        for (int i = 0; i < 8; i++) {
            int gr = r0 + ty * 8 + i;
            if (gr < M) {
                float v = acc[i][j];
                if (MODE == 1) {
                    v = fmaxf(v + bi, 0.f) * sc + sh;
                    g_h[(size_t)gr * 96 + c] = v;
                } else if (MODE == 0) {
                    g_yh[(size_t)gr * 96 + c] = __float2half_rn(v);
                } else {
                    g_hth[(size_t)gr * 96 + c] = __float2half_rn(v);
                }
            }
        }
    }

    if (MODE == 2) {
        // fused als/ald: warp-reduce fp32 acc rows against a_src / a_dst (exact)
        float asr0 = g_ASRC[lane * 3 + 0], asr1 = g_ASRC[lane * 3 + 1], asr2 = g_ASRC[lane * 3 + 2];
        float ads0 = g_ADST[lane * 3 + 0], ads1 = g_ADST[lane * 3 + 1], ads2 = g_ADST[lane * 3 + 2];
#pragma unroll
        for (int i = 0; i < 8; i++) {
            float ps = acc[i][0] * asr0 + acc[i][1] * asr1 + acc[i][2] * asr2;
            float pd = acc[i][0] * ads0 + acc[i][1] * ads1 + acc[i][2] * ads2;
#pragma unroll
            for (int o = 16; o; o >>= 1) {
                ps += __shfl_xor_sync(0xffffffffu, ps, o);
                pd += __shfl_xor_sync(0xffffffffu, pd, o);
            }
            int gr = r0 + ty * 8 + i;
            if (lane == 0 && gr < M) { g_als[gr] = ps; g_ald[gr] = pd; }
        }
    }
}

// ---------------- GAT: warp per node, single pass, fp16 gathers, fp32 accumulate ---
__global__ void gat_kernel()
{
    int n = (blockIdx.x * blockDim.x + threadIdx.x) >> 5;
    int lane = threadIdx.x & 31;
    if (n >= NN) return;
    int p0 = g_rowptr[n], p1 = g_rowptr[n + 1];
    float aldn = g_ald[n];
    float wself = __expf(lrelu(g_als[n] + aldn));

    float4 acc = make_float4(0.f, 0.f, 0.f, 0.f);
    if (lane < 24) {
        float4 v = ldh4(g_hth + (size_t)n * 96 + lane * 4);
        acc.x = wself * v.x; acc.y = wself * v.y;
        acc.z = wself * v.z; acc.w = wself * v.w;
    }
    float ls = 0.f;

    for (int base = p0; base < p1; base += 32) {
        int p = base + lane;
        float wv = 0.f; int sv = 0;
        if (p < p1) {
            sv = g_col[p];
            wv = __expf(lrelu(g_als[sv] + aldn));
        }
        ls += wv;
        int cnt = min(32, p1 - base);
        for (int j = 0; j < cnt; j++) {
            float wj = __shfl_sync(0xffffffffu, wv, j);
            int   sj = __shfl_sync(0xffffffffu, sv, j);
            if (lane < 24) {
                float4 v = ldh4(g_hth + (size_t)sj * 96 + lane * 4);
                acc.x += wj * v.x; acc.y += wj * v.y;
                acc.z += wj * v.z; acc.w += wj * v.w;
            }
        }
    }
#pragma unroll
    for (int o = 16; o; o >>= 1) ls += __shfl_xor_sync(0xffffffffu, ls, o);
    float inv = 1.f / (ls + wself);

    if (lane < 24) {
        float4 bb = ((const float4*)g_BG)[lane];
        float4 o;
        o.x = acc.x * inv + bb.x;
        o.y = acc.y * inv + bb.y;
        o.z = acc.z * inv + bb.z;
        o.w = acc.w * inv + bb.w;
        ((float4*)g_ao)[(size_t)n * 24 + lane] = o;
    }
}

// ---------------- global_add_pool: block per graph (batch is sorted) ----------------
template<typename T>
__device__ __forceinline__ int lbound(const T* __restrict__ a, int n, T key)
{
    int lo = 0, hi = n;
    while (lo < hi) {
        int mid = (lo + hi) >> 1;
        if (a[mid] < key) lo = mid + 1; else hi = mid;
    }
    return lo;
}

template<typename T>
__global__ void pool_kernel(const void* __restrict__ batchv)
{
    if (!type_active<T>()) return;
    const T* __restrict__ batch = (const T*)batchv;
    int g = blockIdx.x;
    int tid = threadIdx.x;        // 96 threads
    int lo = lbound<T>(batch, NN, (T)g);
    int hi = lbound<T>(batch, NN, (T)(g + 1));
    float s0 = 0.f, s1 = 0.f, s2 = 0.f, s3 = 0.f;
    int i = lo;
    for (; i + 3 < hi; i += 4) {
        s0 += g_ao[(size_t)(i + 0) * 96 + tid];
        s1 += g_ao[(size_t)(i + 1) * 96 + tid];
        s2 += g_ao[(size_t)(i + 2) * 96 + tid];
        s3 += g_ao[(size_t)(i + 3) * 96 + tid];
    }
    for (; i < hi; i++) s0 += g_ao[(size_t)i * 96 + tid];
    g_gp[g * 96 + tid] = (s0 + s1) + (s2 + s3);
}

// ---------------- fc1 + 3 heads: block per graph ----------------
__global__ void heads_kernel(const float* __restrict__ wfc, const float* __restrict__ bfc,
                             const float* __restrict__ w10, const float* __restrict__ b10,
                             const float* __restrict__ w20, const float* __restrict__ b20,
                             const float* __restrict__ w11, const float* __restrict__ b11,
                             const float* __restrict__ w21, const float* __restrict__ b21,
                             const float* __restrict__ w12, const float* __restrict__ b12,
                             const float* __restrict__ w22, const float* __restrict__ b22,
                             float* __restrict__ dout)
{
    int g = blockIdx.x;
    int tid = threadIdx.x;        // 192 threads
    __shared__ float gp[96];
    __shared__ float gf[192];
    __shared__ float hid[36];
    if (tid < 96) gp[tid] = g_gp[g * 96 + tid];
    __syncthreads();
    if (tid < FC2) {
        float acc = bfc[tid];
        for (int k = 0; k < DIMR; k++) acc += gp[k] * wfc[k * FC2 + tid];
        gf[tid] = fmaxf(acc, 0.f);
    }
    __syncthreads();
    if (tid < 36) {
        int h = tid / 12, u = tid % 12;
        const float* w1 = (h == 0) ? w10 : (h == 1) ? w11 : w12;
        const float* b1 = (h == 0) ? b10 : (h == 1) ? b11 : b12;
        float acc = b1[u];
        for (int k = 0; k < FC2; k++) acc += gf[k] * w1[k * 12 + u];
        hid[tid] = fmaxf(acc, 0.f);
    }
    __syncthreads();
    if (tid < 3) {
        const float* w2 = (tid == 0) ? w20 : (tid == 1) ? w21 : w22;
        const float* b2 = (tid == 0) ? b20 : (tid == 1) ? b21 : b22;
        float acc = b2[0];
        for (int k = 0; k < 12; k++) acc += hid[tid * 12 + k] * w2[k];
        if (tid == 0) acc = 1.f / (1.f + __expf(-acc));
        dout[g * 3 + tid] = acc;
    }
}

// ---------------- launcher (kernel launches ONLY — graph-capturable) ----------------
extern "C" void kernel_launch(void* const* d_in, const int* in_sizes, int n_in,
                              void* d_out, int out_size)
{
    const float* x     = (const float*)d_in[0];
    const void*  ei    = d_in[1];
    const void*  batch = d_in[2];
    const float* w1a = (const float*)d_in[3];
    const float* b1a = (const float*)d_in[4];
    const float* w1b = (const float*)d_in[5];
    const float* b1b = (const float*)d_in[6];
    const float* bng = (const float*)d_in[7];
    const float* bnb = (const float*)d_in[8];
    const float* bnm = (const float*)d_in[9];
    const float* bnv = (const float*)d_in[10];
    const float* wg  = (const float*)d_in[11];
    const float* bg  = (const float*)d_in[12];
    const float* asrc = (const float*)d_in[13];
    const float* adst = (const float*)d_in[14];
    const float* wfc = (const float*)d_in[15];
    const float* bfc = (const float*)d_in[16];
    const float* h0w1 = (const float*)d_in[17];
    const float* h0b1 = (const float*)d_in[18];
    const float* h0w2 = (const float*)d_in[19];
    const float* h0b2 = (const float*)d_in[20];
    const float* h1w1 = (const float*)d_in[21];
    const float* h1b1 = (const float*)d_in[22];
    const float* h1w2 = (const float*)d_in[23];
    const float* h1b2 = (const float*)d_in[24];
    const float* h2w1 = (const float*)d_in[25];
    const float* h2b1 = (const float*)d_in[26];
    const float* h2w2 = (const float*)d_in[27];
    const float* h2b2 = (const float*)d_in[28];
    float* dout = (float*)d_out;

    // dtype detect + weight prep; GEMM0 placed 4th so ncu's fixed skip profiles it
    detect_kernel<<<1, 256>>>((const int*)ei);
    prep_kernel<<<(FIN * DIMP + 255) / 256, 256>>>(w1a, b1a, w1b, b1b, bng, bnb, bnm, bnv,
                                                   wg, bg, asrc, adst);
    zero_deg_kernel<<<(NN / 4 + 255) / 256, 256>>>();
    gemm_kernel<0><<<(NN + 63) / 64, 256>>>(x);

    // CSR build (4 edges per thread)
    hist_kernel<int><<<(EE / 4 + 255) / 256, 256>>>(ei);
    hist_kernel<long long><<<(EE / 4 + 255) / 256, 256>>>(ei);
    block_sum_kernel<<<NBLK, 256>>>();
    scan_partials_kernel<<<1, 128>>>();
    rowptr_kernel<<<NBLK, 256>>>();
    scatter_kernel<int><<<(EE / 4 + 255) / 256, 256>>>(ei);
    scatter_kernel<long long><<<(EE / 4 + 255) / 256, 256>>>(ei);

    // GIN: aggregate y (fp16 table) with fused bias+relu, then GEMM1
    gin_agg_kernel<<<(NN * 32 + 255) / 256, 256>>>();
    gemm_kernel<1><<<(NN + 63) / 64, 256>>>(nullptr);

    // GAT: GEMM2 (fp16 out + fused als/ald), then single-pass softmax-aggregate
    gemm_kernel<2><<<(NN + 63) / 64, 256>>>(nullptr);
    gat_kernel<<<(NN * 32 + 255) / 256, 256>>>();

    // pool + heads
    pool_kernel<int><<<GG, 96>>>(batch);
    pool_kernel<long long><<<GG, 96>>>(batch);
    heads_kernel<<<GG, 192>>>(wfc, bfc, h0w1, h0b1, h0w2, h0b2,
                              h1w1, h1b1, h1w2, h1b2, h2w1, h2b1, h2w2, h2b2, dout);
}

// round 16
// speedup vs baseline: 1.3955x; 1.2482x over previous
#include <cuda_runtime.h>
#include <cuda_fp16.h>
#include <math.h>
#include <stdint.h>

#define NN   100000
#define EE   3200000
#define FIN  128
#define DIMR 95
#define DIMP 96
#define GG   256
#define FC2  190
#define NEG  0.2f
#define BNEPS 1e-5f
#define NBLK 98              // ceil(NN/1024)

// ---------------- scratch (device globals; no allocation allowed) ----------------
__device__ __half g_yh [(size_t)NN * DIMP];    // x @ w1a, fp16 (gather table)
__device__ float  g_t1 [(size_t)NN * DIMP];    // relu(y_i + sum y_j + b1a)
__device__ float  g_h  [(size_t)NN * DIMP];    // BN(relu(t1@w1b+b1b))
__device__ __half g_hth[(size_t)NN * DIMP];    // h@wg, fp16 (gather table)
__device__ float  g_ao [(size_t)NN * DIMP];    // GAT out
__device__ float  g_als[NN], g_ald[NN];
__device__ float  g_gp [GG * DIMP];
__device__ int    g_deg[NN];
__device__ int    g_bsum[128];
__device__ int    g_boff[128];
__device__ int    g_rowptr[NN + 1];
__device__ int    g_cursor[NN];
__device__ int    g_col[EE];
__device__ float  g_W1[FIN * DIMP];
__device__ float  g_W2[DIMP * DIMP];
__device__ float  g_W3[DIMP * DIMP];
__device__ float  g_B1[DIMP], g_B2[DIMP], g_BNS[DIMP], g_BNT[DIMP];
__device__ float  g_ASRC[DIMP], g_ADST[DIMP], g_BG[DIMP];
__device__ int    g_is64;   // 1 if edge_index/batch are int64, 0 if int32

__device__ __forceinline__ float lrelu(float v) { return v > 0.f ? v : NEG * v; }

// load 4 fp16 cols (8B) and convert to float4
__device__ __forceinline__ float4 ldh4(const __half* p)
{
    uint2 u = *(const uint2*)p;
    __half2 h0 = *(__half2*)&u.x, h1 = *(__half2*)&u.y;
    float2 f0 = __half22float2(h0), f1 = __half22float2(h1);
    return make_float4(f0.x, f0.y, f1.x, f1.y);
}

// ---------------- dtype detection ----------------
__global__ void detect_kernel(const int* __restrict__ ei32)
{
    int tid = threadIdx.x;   // 256 threads
    int ok = (ei32[2 * tid + 1] == 0) ? 1 : 0;
    int cnt = __syncthreads_count(ok);
    if (tid == 0) g_is64 = (cnt == 256) ? 1 : 0;
}

template<typename T>
__device__ __forceinline__ bool type_active() { return g_is64 == (sizeof(T) == 8 ? 1 : 0); }

// ---------------- weight prep: pad everything to width 96, fold BN ----------------
__global__ void prep_kernel(const float* __restrict__ w1a, const float* __restrict__ b1a,
                            const float* __restrict__ w1b, const float* __restrict__ b1b,
                            const float* __restrict__ bng, const float* __restrict__ bnb,
                            const float* __restrict__ bnm, const float* __restrict__ bnv,
                            const float* __restrict__ wg,  const float* __restrict__ bg,
                            const float* __restrict__ asrc,const float* __restrict__ adst)
{
    int i = blockIdx.x * blockDim.x + threadIdx.x;
    if (i < FIN * DIMP) {
        int r = i / DIMP, c = i % DIMP;
        g_W1[i] = (c < DIMR) ? w1a[r * DIMR + c] : 0.f;
    }
    if (i < DIMP * DIMP) {
        int r = i / DIMP, c = i % DIMP;
        bool ok = (r < DIMR && c < DIMR);
        g_W2[i] = ok ? w1b[r * DIMR + c] : 0.f;
        g_W3[i] = ok ? wg [r * DIMR + c] : 0.f;
    }
    if (i < DIMP) {
        bool ok = i < DIMR;
        g_B1[i] = ok ? b1a[i] : 0.f;
        g_B2[i] = ok ? b1b[i] : 0.f;
        float s = ok ? bng[i] * rsqrtf(bnv[i] + BNEPS) : 0.f;
        g_BNS[i] = s;
        g_BNT[i] = ok ? (bnb[i] - bnm[i] * s) : 0.f;
        g_ASRC[i] = ok ? asrc[i] : 0.f;
        g_ADST[i] = ok ? adst[i] : 0.f;
        g_BG[i]   = ok ? bg[i]   : 0.f;
    }
}

// ---------------- CSR build (vectorized: 4 edges/thread, 16B loads) ----------------
__global__ void zero_deg_kernel()
{
    int i = blockIdx.x * blockDim.x + threadIdx.x;   // int4 stores
    if (i < NN / 4) ((int4*)g_deg)[i] = make_int4(0, 0, 0, 0);
}

template<typename T>
__global__ void hist_kernel(const void* __restrict__ eiv)
{
    if (!type_active<T>()) return;
    int e4 = (blockIdx.x * blockDim.x + threadIdx.x) * 4;
    if (e4 >= EE) return;
    int d0, d1, d2, d3;
    if (sizeof(T) == 8) {
        const longlong2* p = (const longlong2*)((const long long*)eiv + EE + e4);
        longlong2 a = p[0], b = p[1];
        d0 = (int)a.x; d1 = (int)a.y; d2 = (int)b.x; d3 = (int)b.y;
    } else {
        int4 a = *(const int4*)((const int*)eiv + EE + e4);
        d0 = a.x; d1 = a.y; d2 = a.z; d3 = a.w;
    }
    atomicAdd(&g_deg[d0], 1);
    atomicAdd(&g_deg[d1], 1);
    atomicAdd(&g_deg[d2], 1);
    atomicAdd(&g_deg[d3], 1);
}

__device__ __forceinline__ int warp_incl_scan(int v, int lane)
{
#pragma unroll
    for (int o = 1; o < 32; o <<= 1) {
        int t = __shfl_up_sync(0xffffffffu, v, o);
        if (lane >= o) v += t;
    }
    return v;
}

__global__ void block_sum_kernel()
{
    int blk = blockIdx.x, tid = threadIdx.x;           // 256 threads
    int lane = tid & 31, wid = tid >> 5;
    int i0 = blk * 1024 + tid * 4;
    int s = 0;
#pragma unroll
    for (int k = 0; k < 4; k++) {
        int i = i0 + k;
        if (i < NN) s += g_deg[i];
    }
#pragma unroll
    for (int o = 16; o; o >>= 1) s += __shfl_xor_sync(0xffffffffu, s, o);
    __shared__ int ws[8];
    if (lane == 0) ws[wid] = s;
    __syncthreads();
    if (tid == 0) {
        int t = 0;
        for (int w = 0; w < 8; w++) t += ws[w];
        g_bsum[blk] = t;
    }
}

__global__ void scan_partials_kernel()
{
    __shared__ int sm[128];
    int tid = threadIdx.x;
    int v = (tid < NBLK) ? g_bsum[tid] : 0;
    sm[tid] = v;
    __syncthreads();
#pragma unroll
    for (int o = 1; o < 128; o <<= 1) {
        int t = (tid >= o) ? sm[tid - o] : 0;
        __syncthreads();
        sm[tid] += t;
        __syncthreads();
    }
    if (tid < NBLK) g_boff[tid] = sm[tid] - v;
}

__global__ void rowptr_kernel()
{
    int blk = blockIdx.x, tid = threadIdx.x;           // 256 threads
    int lane = tid & 31, wid = tid >> 5;
    int i0 = blk * 1024 + tid * 4;
    int v[4];
#pragma unroll
    for (int k = 0; k < 4; k++) {
        int i = i0 + k;
        v[k] = (i < NN) ? g_deg[i] : 0;
    }
    int tsum = v[0] + v[1] + v[2] + v[3];
    int incl = warp_incl_scan(tsum, lane);
    __shared__ int ws[8];
    if (lane == 31) ws[wid] = incl;
    __syncthreads();
    if (wid == 0) {
        int w = (lane < 8) ? ws[lane] : 0;
        int wi = warp_incl_scan(w, lane);
        if (lane < 8) ws[lane] = wi - w;   // exclusive warp offsets
    }
    __syncthreads();
    int base = g_boff[blk] + ws[wid] + (incl - tsum);
    int pre = 0;
#pragma unroll
    for (int k = 0; k < 4; k++) {
        int i = i0 + k;
        if (i < NN) {
            int excl = base + pre;
            g_rowptr[i] = excl;
            g_cursor[i] = excl;
            if (i == NN - 1) g_rowptr[NN] = excl + v[k];
        }
        pre += v[k];
    }
}

template<typename T>
__global__ void scatter_kernel(const void* __restrict__ eiv)
{
    if (!type_active<T>()) return;
    int e4 = (blockIdx.x * blockDim.x + threadIdx.x) * 4;
    if (e4 >= EE) return;
    int s0, s1, s2, s3, d0, d1, d2, d3;
    if (sizeof(T) == 8) {
        const longlong2* ps = (const longlong2*)((const long long*)eiv + e4);
        const longlong2* pd = (const longlong2*)((const long long*)eiv + EE + e4);
        longlong2 a = ps[0], b = ps[1], c = pd[0], d = pd[1];
        s0 = (int)a.x; s1 = (int)a.y; s2 = (int)b.x; s3 = (int)b.y;
        d0 = (int)c.x; d1 = (int)c.y; d2 = (int)d.x; d3 = (int)d.y;
    } else {
        int4 a = *(const int4*)((const int*)eiv + e4);
        int4 c = *(const int4*)((const int*)eiv + EE + e4);
        s0 = a.x; s1 = a.y; s2 = a.z; s3 = a.w;
        d0 = c.x; d1 = c.y; d2 = c.z; d3 = c.w;
    }
    g_col[atomicAdd(&g_cursor[d0], 1)] = s0;
    g_col[atomicAdd(&g_cursor[d1], 1)] = s1;
    g_col[atomicAdd(&g_cursor[d2], 1)] = s2;
    g_col[atomicAdd(&g_cursor[d3], 1)] = s3;
}

// ---------------- GIN aggregation: warp per node, fp16 gathers, fp32 accumulate ----
__global__ void gin_agg_kernel()
{
    int n = (blockIdx.x * blockDim.x + threadIdx.x) >> 5;
    int lane = threadIdx.x & 31;
    if (n >= NN) return;
    int p0 = g_rowptr[n], p1 = g_rowptr[n + 1];
    if (lane < 24) {
        float4 acc = ldh4(g_yh + (size_t)n * 96 + lane * 4);
        for (int p = p0; p < p1; p++) {
            int s = g_col[p];
            float4 v = ldh4(g_yh + (size_t)s * 96 + lane * 4);
            acc.x += v.x; acc.y += v.y; acc.z += v.z; acc.w += v.w;
        }
        float4 bb = ((const float4*)g_B1)[lane];
        float4 o;
        o.x = fmaxf(acc.x + bb.x, 0.f);
        o.y = fmaxf(acc.y + bb.y, 0.f);
        o.z = fmaxf(acc.z + bb.z, 0.f);
        o.w = fmaxf(acc.w + bb.w, 0.f);
        ((float4*)g_t1)[(size_t)n * 24 + lane] = o;
    }
}

// ---------------- fp16 tensor-core GEMM: C[M,96] = epi(A[M,K] @ W[K,96]) -----------
// BM=64, BN=96, BK=16, 256 threads = 8 warps (4 M-slabs x 2 N-slabs of 48).
// Tiles stored fp16 in smem; fragments via ldmatrix (A: x4, B: x4.trans).
// mma.sync.m16n8k16.f32.f16.f16.f32, fp32 accumulate.
// MODE 0: A=x(ext) K=128 W=g_W1 C=g_yh  (fp16 out)
// MODE 1: A=g_t1   K=96  W=g_W2 C=g_h   epi=BN(relu+bias), fp32 out
// MODE 2: A=g_h    K=96  W=g_W3 C=g_hth (fp16 out)
template<int MODE>
__global__ __launch_bounds__(256, 3)
void gemm_kernel(const float* __restrict__ Aext)
{
    const float* __restrict__ A = (MODE == 0) ? Aext : (MODE == 1) ? g_t1 : g_h;
    const float* __restrict__ W = (MODE == 0) ? g_W1 : (MODE == 1) ? g_W2 : g_W3;
    const int K = (MODE == 0) ? FIN : DIMP;
    const int M = NN;

    __shared__ __align__(16) __half Ah[2][64][24];    // [m][k], pad 24 (48B rows)
    __shared__ __align__(16) __half Bh[2][16][104];   // [k][n], pad 104 (208B rows)

    int tid = threadIdx.x;
    int w = tid >> 5, lane = tid & 31;
    int g = lane >> 2, t = lane & 3;
    int mbase = (w & 3) * 16;          // warp M-slab
    int nbase = (w >> 2) * 48;         // warp N-slab
    int r0 = blockIdx.x * 64;

    // A-load geometry: 64x16 tile, 1 float4 -> 4 halfs per thread
    const int arow = tid >> 2, akq = tid & 3;
    const int gra = r0 + arow;
    // B-load geometry: 16x96 tile = 384 float4; tid and tid+256 (if <384)
    const int brow0 = tid / 24,  bc0 = tid % 24;
    const bool bv1 = (tid + 256) < 384;
    const int brow1 = (tid + 256) / 24, bc1 = (tid + 256) % 24;

    // ldmatrix addressing
    int reg = lane >> 3;
    unsigned a_sh = (unsigned)__cvta_generic_to_shared(&Ah[0][0][0]);
    unsigned b_sh = (unsigned)__cvta_generic_to_shared(&Bh[0][0][0]);
    // A x4: m0=(m0-7,k0-7) m1=(m8-15,k0-7) m2=(m0-7,k8-15) m3=(m8-15,k8-15)
    unsigned a_off = ((unsigned)((mbase + (lane & 7) + (reg & 1) * 8) * 24
                                 + (reg >> 1) * 8)) * 2u;
    // B x4.trans: m0=(k0-7,n0) m1=(k8-15,n0) m2=(k0-7,n8) m3=(k8-15,n8)
    unsigned b_off = ((unsigned)(((reg & 1) * 8 + (lane & 7)) * 104
                                 + nbase + (reg >> 1) * 8)) * 2u;

    float4 pa, pb0, pb1;
    const float4 z4 = make_float4(0.f, 0.f, 0.f, 0.f);

    pa  = (gra < M) ? *(const float4*)(A + (size_t)gra * K + akq * 4) : z4;
    pb0 = *(const float4*)(W + (size_t)brow0 * 96 + bc0 * 4);
    pb1 = bv1 ? *(const float4*)(W + (size_t)brow1 * 96 + bc1 * 4) : z4;

    // store tile 0 (fp32 -> fp16)
    {
        __half2 h01 = __floats2half2_rn(pa.x, pa.y), h23 = __floats2half2_rn(pa.z, pa.w);
        *(__half2*)&Ah[0][arow][akq * 4]     = h01;
        *(__half2*)&Ah[0][arow][akq * 4 + 2] = h23;
        __half2 b01 = __floats2half2_rn(pb0.x, pb0.y), b23 = __floats2half2_rn(pb0.z, pb0.w);
        *(__half2*)&Bh[0][brow0][bc0 * 4]     = b01;
        *(__half2*)&Bh[0][brow0][bc0 * 4 + 2] = b23;
        if (bv1) {
            __half2 c01 = __floats2half2_rn(pb1.x, pb1.y), c23 = __floats2half2_rn(pb1.z, pb1.w);
            *(__half2*)&Bh[0][brow1][bc1 * 4]     = c01;
            *(__half2*)&Bh[0][brow1][bc1 * 4 + 2] = c23;
        }
    }
    __syncthreads();

    float acc[6][4];
#pragma unroll
    for (int j = 0; j < 6; j++)
#pragma unroll
        for (int q = 0; q < 4; q++) acc[j][q] = 0.f;

    const int ntile = K >> 4;
#pragma unroll 1
    for (int kt = 0; kt < ntile; kt++) {
        int cur = kt & 1, nxt = cur ^ 1;
        bool more = (kt + 1) < ntile;
        if (more) {
            int kb = (kt + 1) * 16;
            pa  = (gra < M) ? *(const float4*)(A + (size_t)gra * K + kb + akq * 4) : z4;
            pb0 = *(const float4*)(W + (size_t)(kb + brow0) * 96 + bc0 * 4);
            pb1 = bv1 ? *(const float4*)(W + (size_t)(kb + brow1) * 96 + bc1 * 4) : z4;
        }
        unsigned abuf = a_sh + (unsigned)cur * (64 * 24 * 2) + a_off;
        unsigned bbuf = b_sh + (unsigned)cur * (16 * 104 * 2) + b_off;
        unsigned a0, a1, a2, a3;
        asm volatile("ldmatrix.sync.aligned.m8n8.x4.shared.b16 {%0,%1,%2,%3}, [%4];"
                     : "=r"(a0), "=r"(a1), "=r"(a2), "=r"(a3) : "r"(abuf));
#pragma unroll
        for (int jj = 0; jj < 3; jj++) {
            unsigned b0, b1, b2, b3;
            asm volatile("ldmatrix.sync.aligned.m8n8.x4.trans.shared.b16 {%0,%1,%2,%3}, [%4];"
                         : "=r"(b0), "=r"(b1), "=r"(b2), "=r"(b3)
                         : "r"(bbuf + (unsigned)jj * 32));
            asm("mma.sync.aligned.m16n8k16.row.col.f32.f16.f16.f32 "
                "{%0,%1,%2,%3}, {%4,%5,%6,%7}, {%8,%9}, {%0,%1,%2,%3};"
                : "+f"(acc[2 * jj][0]), "+f"(acc[2 * jj][1]),
                  "+f"(acc[2 * jj][2]), "+f"(acc[2 * jj][3])
                : "r"(a0), "r"(a1), "r"(a2), "r"(a3), "r"(b0), "r"(b1));
            asm("mma.sync.aligned.m16n8k16.row.col.f32.f16.f16.f32 "
                "{%0,%1,%2,%3}, {%4,%5,%6,%7}, {%8,%9}, {%0,%1,%2,%3};"
                : "+f"(acc[2 * jj + 1][0]), "+f"(acc[2 * jj + 1][1]),
                  "+f"(acc[2 * jj + 1][2]), "+f"(acc[2 * jj + 1][3])
                : "r"(a0), "r"(a1), "r"(a2), "r"(a3), "r"(b2), "r"(b3));
        }
        if (more) {
            __half2 h01 = __floats2half2_rn(pa.x, pa.y), h23 = __floats2half2_rn(pa.z, pa.w);
            *(__half2*)&Ah[nxt][arow][akq * 4]     = h01;
            *(__half2*)&Ah[nxt][arow][akq * 4 + 2] = h23;
            __half2 b01 = __floats2half2_rn(pb0.x, pb0.y), b23 = __floats2half2_rn(pb0.z, pb0.w);
            *(__half2*)&Bh[nxt][brow0][bc0 * 4]     = b01;
            *(__half2*)&Bh[nxt][brow0][bc0 * 4 + 2] = b23;
            if (bv1) {
                __half2 c01 = __floats2half2_rn(pb1.x, pb1.y), c23 = __floats2half2_rn(pb1.z, pb1.w);
                *(__half2*)&Bh[nxt][brow1][bc1 * 4]     = c01;
                *(__half2*)&Bh[nxt][brow1][bc1 * 4 + 2] = c23;
            }
            __syncthreads();
        }
    }

    // epilogue: c0=(g,2t) c1=(g,2t+1) c2=(g+8,2t) c3=(g+8,2t+1) per n8-tile
    int rA = r0 + mbase + g;
    int rB = rA + 8;
#pragma unroll
    for (int j = 0; j < 6; j++) {
        int c = nbase + j * 8 + 2 * t;
        float v0 = acc[j][0], v1 = acc[j][1], v2 = acc[j][2], v3 = acc[j][3];
        if (MODE == 1) {
            float b0 = g_B2[c],  b1 = g_B2[c + 1];
            float s0 = g_BNS[c], s1 = g_BNS[c + 1];
            float t0 = g_BNT[c], t1 = g_BNT[c + 1];
            v0 = fmaxf(v0 + b0, 0.f) * s0 + t0;
            v1 = fmaxf(v1 + b1, 0.f) * s1 + t1;
            v2 = fmaxf(v2 + b0, 0.f) * s0 + t0;
            v3 = fmaxf(v3 + b1, 0.f) * s1 + t1;
            if (rA < M) *(float2*)(g_h + (size_t)rA * 96 + c) = make_float2(v0, v1);
            if (rB < M) *(float2*)(g_h + (size_t)rB * 96 + c) = make_float2(v2, v3);
        } else {
            __half* dst = (MODE == 0) ? g_yh : g_hth;
            if (rA < M) *(__half2*)(dst + (size_t)rA * 96 + c) = __floats2half2_rn(v0, v1);
            if (rB < M) *(__half2*)(dst + (size_t)rB * 96 + c) = __floats2half2_rn(v2, v3);
        }
    }
}

// ---------------- attention logits: als/ald per node (from fp16 ht table) ----------
__global__ void alsald_kernel()
{
    int n = (blockIdx.x * blockDim.x + threadIdx.x) >> 5;
    int lane = threadIdx.x & 31;
    if (n >= NN) return;
    float ps = 0.f, pd = 0.f;
    if (lane < 24) {
        float4 v  = ldh4(g_hth + (size_t)n * 96 + lane * 4);
        float4 as = ((const float4*)g_ASRC)[lane];
        float4 ad = ((const float4*)g_ADST)[lane];
        ps = v.x * as.x + v.y * as.y + v.z * as.z + v.w * as.w;
        pd = v.x * ad.x + v.y * ad.y + v.z * ad.z + v.w * ad.w;
    }
#pragma unroll
    for (int o = 16; o; o >>= 1) {
        ps += __shfl_xor_sync(0xffffffffu, ps, o);
        pd += __shfl_xor_sync(0xffffffffu, pd, o);
    }
    if (lane == 0) { g_als[n] = ps; g_ald[n] = pd; }
}

// ---------------- GAT: warp per node, single pass, fp16 gathers, fp32 accumulate ---
__global__ void gat_kernel()
{
    int n = (blockIdx.x * blockDim.x + threadIdx.x) >> 5;
    int lane = threadIdx.x & 31;
    if (n >= NN) return;
    int p0 = g_rowptr[n], p1 = g_rowptr[n + 1];
    float aldn = g_ald[n];
    float wself = __expf(lrelu(g_als[n] + aldn));

    float4 acc = make_float4(0.f, 0.f, 0.f, 0.f);
    if (lane < 24) {
        float4 v = ldh4(g_hth + (size_t)n * 96 + lane * 4);
        acc.x = wself * v.x; acc.y = wself * v.y;
        acc.z = wself * v.z; acc.w = wself * v.w;
    }
    float ls = 0.f;

    for (int base = p0; base < p1; base += 32) {
        int p = base + lane;
        float wv = 0.f; int sv = 0;
        if (p < p1) {
            sv = g_col[p];
            wv = __expf(lrelu(g_als[sv] + aldn));
        }
        ls += wv;
        int cnt = min(32, p1 - base);
        for (int j = 0; j < cnt; j++) {
            float wj = __shfl_sync(0xffffffffu, wv, j);
            int   sj = __shfl_sync(0xffffffffu, sv, j);
            if (lane < 24) {
                float4 v = ldh4(g_hth + (size_t)sj * 96 + lane * 4);
                acc.x += wj * v.x; acc.y += wj * v.y;
                acc.z += wj * v.z; acc.w += wj * v.w;
            }
        }
    }
#pragma unroll
    for (int o = 16; o; o >>= 1) ls += __shfl_xor_sync(0xffffffffu, ls, o);
    float inv = 1.f / (ls + wself);

    if (lane < 24) {
        float4 bb = ((const float4*)g_BG)[lane];
        float4 o;
        o.x = acc.x * inv + bb.x;
        o.y = acc.y * inv + bb.y;
        o.z = acc.z * inv + bb.z;
        o.w = acc.w * inv + bb.w;
        ((float4*)g_ao)[(size_t)n * 24 + lane] = o;
    }
}

// ---------------- global_add_pool: block per graph (batch is sorted) ----------------
template<typename T>
__device__ __forceinline__ int lbound(const T* __restrict__ a, int n, T key)
{
    int lo = 0, hi = n;
    while (lo < hi) {
        int mid = (lo + hi) >> 1;
        if (a[mid] < key) lo = mid + 1; else hi = mid;
    }
    return lo;
}

template<typename T>
__global__ void pool_kernel(const void* __restrict__ batchv)
{
    if (!type_active<T>()) return;
    const T* __restrict__ batch = (const T*)batchv;
    int g = blockIdx.x;
    int tid = threadIdx.x;        // 96 threads
    int lo = lbound<T>(batch, NN, (T)g);
    int hi = lbound<T>(batch, NN, (T)(g + 1));
    float s0 = 0.f, s1 = 0.f, s2 = 0.f, s3 = 0.f;
    int i = lo;
    for (; i + 3 < hi; i += 4) {
        s0 += g_ao[(size_t)(i + 0) * 96 + tid];
        s1 += g_ao[(size_t)(i + 1) * 96 + tid];
        s2 += g_ao[(size_t)(i + 2) * 96 + tid];
        s3 += g_ao[(size_t)(i + 3) * 96 + tid];
    }
    for (; i < hi; i++) s0 += g_ao[(size_t)i * 96 + tid];
    g_gp[g * 96 + tid] = (s0 + s1) + (s2 + s3);
}

// ---------------- fc1 + 3 heads: block per graph ----------------
__global__ void heads_kernel(const float* __restrict__ wfc, const float* __restrict__ bfc,
                             const float* __restrict__ w10, const float* __restrict__ b10,
                             const float* __restrict__ w20, const float* __restrict__ b20,
                             const float* __restrict__ w11, const float* __restrict__ b11,
                             const float* __restrict__ w21, const float* __restrict__ b21,
                             const float* __restrict__ w12, const float* __restrict__ b12,
                             const float* __restrict__ w22, const float* __restrict__ b22,
                             float* __restrict__ dout)
{
    int g = blockIdx.x;
    int tid = threadIdx.x;        // 192 threads
    __shared__ float gp[96];
    __shared__ float gf[192];
    __shared__ float hid[36];
    if (tid < 96) gp[tid] = g_gp[g * 96 + tid];
    __syncthreads();
    if (tid < FC2) {
        float acc = bfc[tid];
        for (int k = 0; k < DIMR; k++) acc += gp[k] * wfc[k * FC2 + tid];
        gf[tid] = fmaxf(acc, 0.f);
    }
    __syncthreads();
    if (tid < 36) {
        int h = tid / 12, u = tid % 12;
        const float* w1 = (h == 0) ? w10 : (h == 1) ? w11 : w12;
        const float* b1 = (h == 0) ? b10 : (h == 1) ? b11 : b12;
        float acc = b1[u];
        for (int k = 0; k < FC2; k++) acc += gf[k] * w1[k * 12 + u];
        hid[tid] = fmaxf(acc, 0.f);
    }
    __syncthreads();
    if (tid < 3) {
        const float* w2 = (tid == 0) ? w20 : (tid == 1) ? w21 : w22;
        const float* b2 = (tid == 0) ? b20 : (tid == 1) ? b21 : b22;
        float acc = b2[0];
        for (int k = 0; k < 12; k++) acc += hid[tid * 12 + k] * w2[k];
        if (tid == 0) acc = 1.f / (1.f + __expf(-acc));
        dout[g * 3 + tid] = acc;
    }
}

// ---------------- launcher (kernel launches ONLY — graph-capturable) ----------------
extern "C" void kernel_launch(void* const* d_in, const int* in_sizes, int n_in,
                              void* d_out, int out_size)
{
    const float* x     = (const float*)d_in[0];
    const void*  ei    = d_in[1];
    const void*  batch = d_in[2];
    const float* w1a = (const float*)d_in[3];
    const float* b1a = (const float*)d_in[4];
    const float* w1b = (const float*)d_in[5];
    const float* b1b = (const float*)d_in[6];
    const float* bng = (const float*)d_in[7];
    const float* bnb = (const float*)d_in[8];
    const float* bnm = (const float*)d_in[9];
    const float* bnv = (const float*)d_in[10];
    const float* wg  = (const float*)d_in[11];
    const float* bg  = (const float*)d_in[12];
    const float* asrc = (const float*)d_in[13];
    const float* adst = (const float*)d_in[14];
    const float* wfc = (const float*)d_in[15];
    const float* bfc = (const float*)d_in[16];
    const float* h0w1 = (const float*)d_in[17];
    const float* h0b1 = (const float*)d_in[18];
    const float* h0w2 = (const float*)d_in[19];
    const float* h0b2 = (const float*)d_in[20];
    const float* h1w1 = (const float*)d_in[21];
    const float* h1b1 = (const float*)d_in[22];
    const float* h1w2 = (const float*)d_in[23];
    const float* h1b2 = (const float*)d_in[24];
    const float* h2w1 = (const float*)d_in[25];
    const float* h2b1 = (const float*)d_in[26];
    const float* h2w2 = (const float*)d_in[27];
    const float* h2b2 = (const float*)d_in[28];
    float* dout = (float*)d_out;

    // dtype detect + weight prep; GEMM0 placed 4th so ncu's fixed skip profiles it
    detect_kernel<<<1, 256>>>((const int*)ei);
    prep_kernel<<<(FIN * DIMP + 255) / 256, 256>>>(w1a, b1a, w1b, b1b, bng, bnb, bnm, bnv,
                                                   wg, bg, asrc, adst);
    zero_deg_kernel<<<(NN / 4 + 255) / 256, 256>>>();
    gemm_kernel<0><<<(NN + 63) / 64, 256>>>(x);

    // CSR build (4 edges per thread)
    hist_kernel<int><<<(EE / 4 + 255) / 256, 256>>>(ei);
    hist_kernel<long long><<<(EE / 4 + 255) / 256, 256>>>(ei);
    block_sum_kernel<<<NBLK, 256>>>();
    scan_partials_kernel<<<1, 128>>>();
    rowptr_kernel<<<NBLK, 256>>>();
    scatter_kernel<int><<<(EE / 4 + 255) / 256, 256>>>(ei);
    scatter_kernel<long long><<<(EE / 4 + 255) / 256, 256>>>(ei);

    // GIN: aggregate y (fp16 table) with fused bias+relu, then GEMM1
    gin_agg_kernel<<<(NN * 32 + 255) / 256, 256>>>();
    gemm_kernel<1><<<(NN + 63) / 64, 256>>>(nullptr);

    // GAT: GEMM2 (fp16 out), als/ald, then single-pass softmax-aggregate
    gemm_kernel<2><<<(NN + 63) / 64, 256>>>(nullptr);
    alsald_kernel<<<(NN * 32 + 255) / 256, 256>>>();
    gat_kernel<<<(NN * 32 + 255) / 256, 256>>>();

    // pool + heads
    pool_kernel<int><<<GG, 96>>>(batch);
    pool_kernel<long long><<<GG, 96>>>(batch);
    heads_kernel<<<GG, 192>>>(wfc, bfc, h0w1, h0b1, h0w2, h0b2,
                              h1w1, h1b1, h1w2, h1b2, h2w1, h2b1, h2w2, h2b2, dout);
}